// round 1
// baseline (speedup 1.0000x reference)
#include <cuda_runtime.h>

#define BATCH 4
#define SEQ   2048
#define FD    256
#define NH    4
#define DH    64
#define CHK   256
#define NCHUNK 8
#define QT    32

// ---------------- device scratch (no allocations allowed) ----------------
__device__ float g_q[BATCH*SEQ*FD];
__device__ float g_k[BATCH*SEQ*FD];
__device__ float g_v[BATCH*SEQ*FD];
__device__ float g_ctx[BATCH*SEQ*FD];
__device__ float g_o[BATCH*SEQ*FD];

// ---------------- GEMM: C[m][n] = sum_k A[m][k]*W[n][k] + bias[n] (+resid) ----------------
// A: [M,256] row-major, W: [256,256] row-major (so C = A @ W^T + b)
__global__ void gemm_bias_kernel(const float* __restrict__ A,
                                 const float* __restrict__ W,
                                 const float* __restrict__ bias,
                                 const float* __restrict__ resid,
                                 float* __restrict__ C) {
  __shared__ float As[64][17];
  __shared__ float Ws[64][17];
  const int tid = threadIdx.x;
  const int tx = tid & 15, ty = tid >> 4;
  const int m0 = blockIdx.y * 64, n0 = blockIdx.x * 64;

  float acc[4][4];
  #pragma unroll
  for (int i = 0; i < 4; i++)
    #pragma unroll
    for (int j = 0; j < 4; j++) acc[i][j] = 0.f;

  const int lrow = tid >> 2;         // 0..63
  const int lkb  = (tid & 3) * 4;    // 0,4,8,12

  for (int k0 = 0; k0 < FD; k0 += 16) {
    float4 a4 = *(const float4*)&A[(size_t)(m0 + lrow) * FD + k0 + lkb];
    float4 w4 = *(const float4*)&W[(size_t)(n0 + lrow) * FD + k0 + lkb];
    As[lrow][lkb + 0] = a4.x; As[lrow][lkb + 1] = a4.y;
    As[lrow][lkb + 2] = a4.z; As[lrow][lkb + 3] = a4.w;
    Ws[lrow][lkb + 0] = w4.x; Ws[lrow][lkb + 1] = w4.y;
    Ws[lrow][lkb + 2] = w4.z; Ws[lrow][lkb + 3] = w4.w;
    __syncthreads();

    #pragma unroll
    for (int kk = 0; kk < 16; kk++) {
      float av[4], wv[4];
      #pragma unroll
      for (int i = 0; i < 4; i++) av[i] = As[ty * 4 + i][kk];
      #pragma unroll
      for (int j = 0; j < 4; j++) wv[j] = Ws[tx * 4 + j][kk];
      #pragma unroll
      for (int i = 0; i < 4; i++)
        #pragma unroll
        for (int j = 0; j < 4; j++) acc[i][j] += av[i] * wv[j];
    }
    __syncthreads();
  }

  #pragma unroll
  for (int i = 0; i < 4; i++) {
    const int m = m0 + ty * 4 + i;
    #pragma unroll
    for (int j = 0; j < 4; j++) {
      const int n = n0 + tx * 4 + j;
      float o = acc[i][j] + bias[n];
      if (resid) o += resid[(size_t)m * FD + n];
      C[(size_t)m * FD + n] = o;
    }
  }
}

// ---------------- Attention ----------------
// Per block: (b, h, tile of 32 queries). 256 threads = 8 warps.
// Warp w owns queries qb*32 + w*4 + {0..3}. Lane l owns keys l + 32*jj within a chunk.
// Shared layout (floats):
//   q_s  [32][65]   padded
//   kc_s [256][65]  padded (conflict-free: key index == lane mod 32)
//   vc_s [256][66]  padded even (float2 reads in ctx pass)
//   p_s  [32][257]  probabilities (broadcast reads in ctx pass)
#define SQ_PITCH  65
#define SK_PITCH  65
#define SV_PITCH  66
#define SP_PITCH  257
#define SM_FLOATS (QT*SQ_PITCH + CHK*SK_PITCH + CHK*SV_PITCH + QT*SP_PITCH)

__global__ void attn_kernel(const float* __restrict__ q,
                            const float* __restrict__ k,
                            const float* __restrict__ v,
                            const int*   __restrict__ adj,
                            float* __restrict__ ctx) {
  extern __shared__ float sm[];
  float* q_s  = sm;
  float* kc_s = q_s  + QT * SQ_PITCH;
  float* vc_s = kc_s + CHK * SK_PITCH;
  float* p_s  = vc_s + CHK * SV_PITCH;

  const int b  = blockIdx.z;
  const int h  = blockIdx.y;
  const int qb = blockIdx.x;
  const int t  = threadIdx.x;
  const int w  = t >> 5;
  const int l  = t & 31;
  const int n0 = qb * QT;

  // load Q tile [32][64]
  {
    const float* qg = q + ((size_t)b * SEQ + n0) * FD + h * DH;
    for (int idx = t; idx < QT * DH; idx += 256) {
      const int r = idx >> 6, d = idx & 63;
      q_s[r * SQ_PITCH + d] = qg[r * FD + d];
    }
  }

  float ctxa[4][2];
  #pragma unroll
  for (int i = 0; i < 4; i++) { ctxa[i][0] = 0.f; ctxa[i][1] = 0.f; }

  const int* adjrow[4];
  #pragma unroll
  for (int i = 0; i < 4; i++)
    adjrow[i] = adj + (size_t)(n0 + w * 4 + i) * SEQ;

  const float* kgb = k + ((size_t)b * SEQ) * FD + h * DH;
  const float* vgb = v + ((size_t)b * SEQ) * FD + h * DH;

  for (int j = 0; j < NCHUNK; ++j) {
    __syncthreads();  // protect kc/vc (prev iter readers) + q_s on first iter

    // cooperative load of K/V chunk [256][64], float4 from global
    {
      const float* kg = kgb + (size_t)(j * CHK) * FD;
      const float* vg = vgb + (size_t)(j * CHK) * FD;
      for (int idx = t; idx < CHK * DH / 4; idx += 256) {
        const int c  = idx >> 4;
        const int d4 = (idx & 15) * 4;
        float4 k4 = *(const float4*)&kg[c * FD + d4];
        float4 v4 = *(const float4*)&vg[c * FD + d4];
        kc_s[c * SK_PITCH + d4 + 0] = k4.x; kc_s[c * SK_PITCH + d4 + 1] = k4.y;
        kc_s[c * SK_PITCH + d4 + 2] = k4.z; kc_s[c * SK_PITCH + d4 + 3] = k4.w;
        vc_s[c * SV_PITCH + d4 + 0] = v4.x; vc_s[c * SV_PITCH + d4 + 1] = v4.y;
        vc_s[c * SV_PITCH + d4 + 2] = v4.z; vc_s[c * SV_PITCH + d4 + 3] = v4.w;
      }
    }
    __syncthreads();

    // ---- score pass: s[i][jj] = q(w*4+i) . k(l+32*jj) ----
    float s[4][8];
    #pragma unroll
    for (int i = 0; i < 4; i++)
      #pragma unroll
      for (int jj = 0; jj < 8; jj++) s[i][jj] = 0.f;

    #pragma unroll 4
    for (int d = 0; d < DH; d++) {
      float qv[4], kv[8];
      #pragma unroll
      for (int i = 0; i < 4; i++) qv[i] = q_s[(w * 4 + i) * SQ_PITCH + d];
      #pragma unroll
      for (int jj = 0; jj < 8; jj++) kv[jj] = kc_s[(l + 32 * jj) * SK_PITCH + d];
      #pragma unroll
      for (int i = 0; i < 4; i++)
        #pragma unroll
        for (int jj = 0; jj < 8; jj++) s[i][jj] += qv[i] * kv[jj];
    }

    // ---- scale, clip, mask, exp, per-query chunk sum ----
    float esum[4] = {0.f, 0.f, 0.f, 0.f};
    #pragma unroll
    for (int i = 0; i < 4; i++) {
      #pragma unroll
      for (int jj = 0; jj < 8; jj++) {
        float sc = s[i][jj] * 0.125f;
        sc = fminf(fmaxf(sc, -10.f), 10.f);
        const int a = adjrow[i][j * CHK + l + 32 * jj];
        if (a == 0) sc = -10.f;
        const float e = __expf(sc);
        s[i][jj] = e;
        esum[i] += e;
      }
    }
    #pragma unroll
    for (int i = 0; i < 4; i++) {
      #pragma unroll
      for (int off = 16; off > 0; off >>= 1)
        esum[i] += __shfl_xor_sync(0xFFFFFFFFu, esum[i], off);
    }

    // write probabilities (warp-private rows)
    #pragma unroll
    for (int i = 0; i < 4; i++) {
      const float r = __fdividef(1.f, esum[i]);
      #pragma unroll
      for (int jj = 0; jj < 8; jj++)
        p_s[(w * 4 + i) * SP_PITCH + l + 32 * jj] = s[i][jj] * r;
    }
    __syncwarp();

    // ---- ctx pass: lane owns dims {2l, 2l+1}; p broadcast per warp ----
    #pragma unroll 4
    for (int c = 0; c < CHK; c++) {
      const float2 vv = *(const float2*)&vc_s[c * SV_PITCH + 2 * l];
      #pragma unroll
      for (int i = 0; i < 4; i++) {
        const float a = p_s[(w * 4 + i) * SP_PITCH + c];
        ctxa[i][0] += a * vv.x;
        ctxa[i][1] += a * vv.y;
      }
    }
  }

  // store ctx: ctx[b, n0+w*4+i, h*64 + 2l + {0,1}]
  #pragma unroll
  for (int i = 0; i < 4; i++) {
    float* cg = ctx + ((size_t)b * SEQ + n0 + w * 4 + i) * FD + h * DH + 2 * l;
    float2 o; o.x = ctxa[i][0]; o.y = ctxa[i][1];
    *(float2*)cg = o;
  }
}

// ---------------- LayerNorm ----------------
__global__ void ln_kernel(const float* __restrict__ o,
                          const float* __restrict__ gamma,
                          const float* __restrict__ beta,
                          float* __restrict__ out) {
  const int row = blockIdx.x;
  const int t = threadIdx.x;
  const int w = t >> 5, l = t & 31;
  const float val = o[(size_t)row * FD + t];

  float s1 = val, s2 = val * val;
  #pragma unroll
  for (int off = 16; off > 0; off >>= 1) {
    s1 += __shfl_xor_sync(0xFFFFFFFFu, s1, off);
    s2 += __shfl_xor_sync(0xFFFFFFFFu, s2, off);
  }
  __shared__ float rs1[8], rs2[8];
  __shared__ float mu_s, rstd_s;
  if (l == 0) { rs1[w] = s1; rs2[w] = s2; }
  __syncthreads();
  if (t == 0) {
    float S1 = 0.f, S2 = 0.f;
    #pragma unroll
    for (int i = 0; i < 8; i++) { S1 += rs1[i]; S2 += rs2[i]; }
    const float mu = S1 * (1.f / FD);
    const float var = S2 * (1.f / FD) - mu * mu;
    mu_s = mu;
    rstd_s = rsqrtf(var + 1e-5f);
  }
  __syncthreads();
  out[(size_t)row * FD + t] = (val - mu_s) * rstd_s * gamma[t] + beta[t];
}

// ---------------- launch ----------------
extern "C" void kernel_launch(void* const* d_in, const int* in_sizes, int n_in,
                              void* d_out, int out_size) {
  (void)in_sizes; (void)n_in; (void)out_size;
  const float* x     = (const float*)d_in[0];
  const int*   adj   = (const int*)  d_in[1];
  const float* Wq    = (const float*)d_in[2];
  const float* bq    = (const float*)d_in[3];
  const float* Wk    = (const float*)d_in[4];
  const float* bk    = (const float*)d_in[5];
  const float* Wv    = (const float*)d_in[6];
  const float* bv    = (const float*)d_in[7];
  const float* Wo    = (const float*)d_in[8];
  const float* bo    = (const float*)d_in[9];
  const float* gamma = (const float*)d_in[10];
  const float* beta  = (const float*)d_in[11];
  float* out = (float*)d_out;

  float *pq, *pk, *pv, *pctx, *po;
  cudaGetSymbolAddress((void**)&pq,   g_q);
  cudaGetSymbolAddress((void**)&pk,   g_k);
  cudaGetSymbolAddress((void**)&pv,   g_v);
  cudaGetSymbolAddress((void**)&pctx, g_ctx);
  cudaGetSymbolAddress((void**)&po,   g_o);

  const dim3 gg(FD / 64, (BATCH * SEQ) / 64);
  gemm_bias_kernel<<<gg, 256>>>(x, Wq, bq, nullptr, pq);
  gemm_bias_kernel<<<gg, 256>>>(x, Wk, bk, nullptr, pk);
  gemm_bias_kernel<<<gg, 256>>>(x, Wv, bv, nullptr, pv);

  const size_t smem = (size_t)SM_FLOATS * sizeof(float);
  cudaFuncSetAttribute(attn_kernel, cudaFuncAttributeMaxDynamicSharedMemorySize,
                       (int)smem);
  const dim3 ga(SEQ / QT, NH, BATCH);
  attn_kernel<<<ga, 256, smem>>>(pq, pk, pv, adj, pctx);

  gemm_bias_kernel<<<gg, 256>>>(pctx, Wo, bo, x, po);
  ln_kernel<<<BATCH * SEQ, 256>>>(po, gamma, beta, out);
}

// round 2
// speedup vs baseline: 1.0469x; 1.0469x over previous
#include <cuda_runtime.h>

#define BATCH 4
#define SEQ   2048
#define FD    256
#define NH    4
#define DH    64
#define CHK   256
#define NCHUNK 8
#define QT    64   // queries per block

typedef unsigned long long ull;

// ---------------- device scratch (no allocations allowed) ----------------
__device__ float g_q[BATCH*SEQ*FD];
__device__ float g_k[BATCH*SEQ*FD];
__device__ float g_v[BATCH*SEQ*FD];
__device__ float g_ctx[BATCH*SEQ*FD];
__device__ float g_o[BATCH*SEQ*FD];
__device__ unsigned g_adjb[SEQ * (SEQ/32)];   // bit-packed adjacency

// ---------------- f32x2 helpers (Blackwell packed fp32) ----------------
__device__ __forceinline__ ull pack2(float x, float y) {
  ull r; asm("mov.b64 %0, {%1, %2};" : "=l"(r) : "f"(x), "f"(y)); return r;
}
__device__ __forceinline__ float2 unpack2(ull v) {
  float2 r; asm("mov.b64 {%0, %1}, %2;" : "=f"(r.x), "=f"(r.y) : "l"(v)); return r;
}
__device__ __forceinline__ void ffma2(ull& d, ull a, ull b) {
  asm("fma.rn.f32x2 %0, %1, %2, %0;" : "+l"(d) : "l"(a), "l"(b));
}
__device__ __forceinline__ ull fmul2(ull a, ull b) {
  ull r; asm("mul.rn.f32x2 %0, %1, %2;" : "=l"(r) : "l"(a), "l"(b)); return r;
}
__device__ __forceinline__ float ex2f(float x) {
  float r; asm("ex2.approx.f32 %0, %1;" : "=f"(r) : "f"(x)); return r;
}
__device__ __forceinline__ float rcpf(float x) {
  float r; asm("rcp.approx.f32 %0, %1;" : "=f"(r) : "f"(x)); return r;
}
union F2U { float2 f; ull u; };

// ---------------- adjacency bit-pack: adjb[row][w] bits = adj[row][32w+k] ----------------
__global__ void pack_adj_kernel(const int* __restrict__ adj,
                                unsigned* __restrict__ adjb) {
  const int idx = blockIdx.x * 256 + threadIdx.x;       // 131072 words
  const int4* p = (const int4*)(adj + (size_t)idx * 32);
  unsigned b = 0;
  #pragma unroll
  for (int u = 0; u < 8; u++) {
    int4 v = p[u];
    b |= (v.x != 0 ? 1u : 0u) << (u*4 + 0);
    b |= (v.y != 0 ? 1u : 0u) << (u*4 + 1);
    b |= (v.z != 0 ? 1u : 0u) << (u*4 + 2);
    b |= (v.w != 0 ? 1u : 0u) << (u*4 + 3);
  }
  adjb[idx] = b;
}

// ---------------- GEMM: C = A @ W^T + bias (+resid), f32x2 inner ----------------
__global__ void __launch_bounds__(256) gemm_bias_kernel(
    const float* __restrict__ A, const float* __restrict__ W,
    const float* __restrict__ bias, const float* __restrict__ resid,
    float* __restrict__ C) {
  __shared__ __align__(16) float As[64][17];
  __shared__ __align__(16) float Wt[16][68];   // Wt[kk][n]
  const int tid = threadIdx.x;
  const int tx = tid & 15, ty = tid >> 4;
  const int m0 = blockIdx.y * 64, n0 = blockIdx.x * 64;
  const int lrow = tid >> 2;
  const int lkb  = (tid & 3) * 4;

  ull acc2[4][2];
  #pragma unroll
  for (int i = 0; i < 4; i++) { acc2[i][0] = 0; acc2[i][1] = 0; }

  for (int k0 = 0; k0 < FD; k0 += 16) {
    float4 a4 = *(const float4*)&A[(size_t)(m0 + lrow) * FD + k0 + lkb];
    float4 w4 = *(const float4*)&W[(size_t)(n0 + lrow) * FD + k0 + lkb];
    As[lrow][lkb+0] = a4.x; As[lrow][lkb+1] = a4.y;
    As[lrow][lkb+2] = a4.z; As[lrow][lkb+3] = a4.w;
    Wt[lkb+0][lrow] = w4.x; Wt[lkb+1][lrow] = w4.y;
    Wt[lkb+2][lrow] = w4.z; Wt[lkb+3][lrow] = w4.w;
    __syncthreads();

    #pragma unroll
    for (int kk = 0; kk < 16; kk++) {
      F2U wv0, wv1;
      wv0.f = *(const float2*)&Wt[kk][tx*4];
      wv1.f = *(const float2*)&Wt[kk][tx*4 + 2];
      #pragma unroll
      for (int i = 0; i < 4; i++) {
        float a = As[ty*4 + i][kk];
        ull a2 = pack2(a, a);
        ffma2(acc2[i][0], wv0.u, a2);
        ffma2(acc2[i][1], wv1.u, a2);
      }
    }
    __syncthreads();
  }

  const int n = n0 + tx * 4;
  const float4 bb = *(const float4*)&bias[n];
  #pragma unroll
  for (int i = 0; i < 4; i++) {
    const int m = m0 + ty*4 + i;
    float2 x0 = unpack2(acc2[i][0]);
    float2 x1 = unpack2(acc2[i][1]);
    float4 o;
    o.x = x0.x + bb.x; o.y = x0.y + bb.y;
    o.z = x1.x + bb.z; o.w = x1.y + bb.w;
    if (resid) {
      float4 rr = *(const float4*)&resid[(size_t)m * FD + n];
      o.x += rr.x; o.y += rr.y; o.z += rr.z; o.w += rr.w;
    }
    *(float4*)&C[(size_t)m * FD + n] = o;
  }
}

// ---------------- Attention ----------------
// Block: (b, h, 64 queries). 256 threads = 8 warps; warp w owns queries qbase=w*8..+7.
// Score: warp tile 8q x 8k, keys as pairs (2kp,2kp+1), lane owns kp = l + 32*jj.
// Ctx:   lane owns dims {l, l+32}; accumulators packed over query pairs.
#define KT_PITCH 258
#define VC_PITCH 65
#define PT_PITCH 66
#define OFF_Q   0
#define OFF_KT  (QT*65)                    // 4160
#define OFF_VC  (OFF_KT + DH*KT_PITCH)     // 20672
#define OFF_PT  (OFF_VC + CHK*VC_PITCH)    // 37312
#define OFF_ADJ (OFF_PT + CHK*PT_PITCH)    // 54208
#define SM_WORDS (OFF_ADJ + QT*8)          // 54720
#define SM_BYTES (SM_WORDS * 4)            // 218880

__global__ void __launch_bounds__(256, 1) attn_kernel(
    const float* __restrict__ q, const float* __restrict__ k,
    const float* __restrict__ v, const unsigned* __restrict__ adjb,
    float* __restrict__ ctx) {
  extern __shared__ __align__(16) float sm[];
  float* q_s = sm + OFF_Q;       // [64][65], pre-scaled by 0.125*log2(e)
  float* kt  = sm + OFF_KT;      // [64 d][258]  kt[d][key]
  float* vc  = sm + OFF_VC;      // [256 c][65]  vc[c][d]
  float* pt  = sm + OFF_PT;      // [256 c][66]  pt[c][swz(q)]
  unsigned* adjb_s = (unsigned*)(sm + OFF_ADJ);  // [64][8]

  const int b  = blockIdx.z;
  const int h  = blockIdx.y;
  const int n0 = blockIdx.x * QT;
  const int t  = threadIdx.x;
  const int w  = t >> 5;
  const int l  = t & 31;
  const int qbase = w * 8;

  const float QSCALE = 0.125f * 1.4426950408889634f;
  const float CLIP   = 14.4269504088896341f;        // 10*log2(e)
  const float ENEG   = 4.5399929762484854e-05f;     // exp(-10)

  // load Q tile [64][64], pre-scaled
  {
    const float* qg = q + ((size_t)b * SEQ + n0) * FD + h * DH;
    #pragma unroll
    for (int it = 0; it < 16; it++) {
      int idx = t + it * 256;
      int r = idx >> 6, d = idx & 63;
      q_s[r * 65 + d] = qg[(size_t)r * FD + d] * QSCALE;
    }
  }

  ull acc[4][2];
  #pragma unroll
  for (int p = 0; p < 4; p++) { acc[p][0] = 0; acc[p][1] = 0; }

  const float* kgb = k + (size_t)b * SEQ * FD + h * DH;
  const float* vgb = v + (size_t)b * SEQ * FD + h * DH;
  const int bit0 = 2 * (l & 15);

  for (int j = 0; j < NCHUNK; ++j) {
    __syncthreads();
    // ---- stage K (transposed), V, adj bits ----
    {
      const float* kg = kgb + (size_t)(j * CHK + t) * FD;
      const float* vg = vgb + (size_t)(j * CHK + t) * FD;
      #pragma unroll
      for (int d4 = 0; d4 < 16; d4++) {
        float4 k4 = *(const float4*)(kg + d4 * 4);
        float4 v4 = *(const float4*)(vg + d4 * 4);
        kt[(d4*4+0) * KT_PITCH + t] = k4.x;
        kt[(d4*4+1) * KT_PITCH + t] = k4.y;
        kt[(d4*4+2) * KT_PITCH + t] = k4.z;
        kt[(d4*4+3) * KT_PITCH + t] = k4.w;
        vc[t * VC_PITCH + d4*4+0] = v4.x;
        vc[t * VC_PITCH + d4*4+1] = v4.y;
        vc[t * VC_PITCH + d4*4+2] = v4.z;
        vc[t * VC_PITCH + d4*4+3] = v4.w;
      }
      #pragma unroll
      for (int it = 0; it < 2; it++) {
        int idx = t + it * 256;                 // 512 words
        int row = idx >> 3, wi = idx & 7;
        adjb_s[idx] = adjb[(size_t)(n0 + row) * (SEQ/32) + j * 8 + wi];
      }
    }
    __syncthreads();

    // ---- score pass: s2[i][jj] = packed scores for keys (2kp, 2kp+1), kp=l+32jj ----
    ull s2[8][4];
    #pragma unroll
    for (int i = 0; i < 8; i++)
      #pragma unroll
      for (int jj = 0; jj < 4; jj++) s2[i][jj] = 0;

    const float* ktl = kt + 2 * l;
    #pragma unroll 4
    for (int d = 0; d < DH; d++) {
      F2U kv[4];
      #pragma unroll
      for (int jj = 0; jj < 4; jj++)
        kv[jj].f = *(const float2*)(ktl + d * KT_PITCH + 64 * jj);
      const float* qp = q_s + qbase * 65 + d;
      #pragma unroll
      for (int i = 0; i < 8; i++) {
        float qd = qp[i * 65];
        ull q2 = pack2(qd, qd);
        #pragma unroll
        for (int jj = 0; jj < 4; jj++) ffma2(s2[i][jj], kv[jj].u, q2);
      }
    }

    // ---- clip, mask, exp, per-chunk softmax; write pT ----
    #pragma unroll
    for (int i = 0; i < 8; i++) {
      const int qq = qbase + i;
      float esum = 0.f;
      #pragma unroll
      for (int jj = 0; jj < 4; jj++) {
        unsigned wd = adjb_s[qq * 8 + 2*jj + (l >> 4)];
        float2 sv = unpack2(s2[i][jj]);
        float t0 = fminf(fmaxf(sv.x, -CLIP), CLIP);
        float t1 = fminf(fmaxf(sv.y, -CLIP), CLIP);
        float e0 = ((wd >> bit0) & 1u)       ? ex2f(t0) : ENEG;
        float e1 = ((wd >> (bit0 + 1)) & 1u) ? ex2f(t1) : ENEG;
        esum += e0 + e1;
        s2[i][jj] = pack2(e0, e1);
      }
      #pragma unroll
      for (int off = 16; off > 0; off >>= 1)
        esum += __shfl_xor_sync(0xFFFFFFFFu, esum, off);
      float r = rcpf(esum);
      ull r2 = pack2(r, r);
      #pragma unroll
      for (int jj = 0; jj < 4; jj++) {
        float2 pv = unpack2(fmul2(s2[i][jj], r2));
        int c0 = 64 * jj + 2 * l;
        int swz = ((c0 >> 4) & 3) << 1;         // same for c0 and c0+1
        pt[c0 * PT_PITCH + (qq ^ swz)]        = pv.x;
        pt[(c0 + 1) * PT_PITCH + (qq ^ swz)]  = pv.y;
      }
    }
    __syncwarp();

    // ---- ctx pass: acc[p][dd] += {p[q0][c],p[q1][c]} * {v[c][d],v[c][d]} ----
    #pragma unroll 2
    for (int c = 0; c < CHK; c++) {
      const int swz = ((c >> 4) & 3) << 1;
      F2U pp[4];
      #pragma unroll
      for (int p = 0; p < 4; p++)
        pp[p].f = *(const float2*)(pt + c * PT_PITCH + ((qbase + 2*p) ^ swz));
      float v0 = vc[c * VC_PITCH + l];
      float v1 = vc[c * VC_PITCH + l + 32];
      ull v02 = pack2(v0, v0);
      ull v12 = pack2(v1, v1);
      #pragma unroll
      for (int p = 0; p < 4; p++) {
        ffma2(acc[p][0], pp[p].u, v02);
        ffma2(acc[p][1], pp[p].u, v12);
      }
    }
  }

  // ---- store ctx ----
  #pragma unroll
  for (int p = 0; p < 4; p++) {
    float2 a0 = unpack2(acc[p][0]);   // dim l    for (q0, q1)
    float2 a1 = unpack2(acc[p][1]);   // dim l+32 for (q0, q1)
    float* cp = ctx + ((size_t)b * SEQ + n0 + qbase + 2*p) * FD + h * DH;
    cp[l]           = a0.x;
    cp[l + 32]      = a1.x;
    cp[FD + l]      = a0.y;
    cp[FD + l + 32] = a1.y;
  }
}

// ---------------- LayerNorm ----------------
__global__ void ln_kernel(const float* __restrict__ o,
                          const float* __restrict__ gamma,
                          const float* __restrict__ beta,
                          float* __restrict__ out) {
  const int row = blockIdx.x;
  const int t = threadIdx.x;
  const int w = t >> 5, l = t & 31;
  const float val = o[(size_t)row * FD + t];

  float s1 = val, s2 = val * val;
  #pragma unroll
  for (int off = 16; off > 0; off >>= 1) {
    s1 += __shfl_xor_sync(0xFFFFFFFFu, s1, off);
    s2 += __shfl_xor_sync(0xFFFFFFFFu, s2, off);
  }
  __shared__ float rs1[8], rs2[8];
  __shared__ float mu_s, rstd_s;
  if (l == 0) { rs1[w] = s1; rs2[w] = s2; }
  __syncthreads();
  if (t == 0) {
    float S1 = 0.f, S2 = 0.f;
    #pragma unroll
    for (int i = 0; i < 8; i++) { S1 += rs1[i]; S2 += rs2[i]; }
    const float mu = S1 * (1.f / FD);
    const float var = S2 * (1.f / FD) - mu * mu;
    mu_s = mu;
    rstd_s = rsqrtf(var + 1e-5f);
  }
  __syncthreads();
  out[(size_t)row * FD + t] = (val - mu_s) * rstd_s * gamma[t] + beta[t];
}

// ---------------- launch ----------------
extern "C" void kernel_launch(void* const* d_in, const int* in_sizes, int n_in,
                              void* d_out, int out_size) {
  (void)in_sizes; (void)n_in; (void)out_size;
  const float* x     = (const float*)d_in[0];
  const int*   adj   = (const int*)  d_in[1];
  const float* Wq    = (const float*)d_in[2];
  const float* bq    = (const float*)d_in[3];
  const float* Wk    = (const float*)d_in[4];
  const float* bk    = (const float*)d_in[5];
  const float* Wv    = (const float*)d_in[6];
  const float* bv    = (const float*)d_in[7];
  const float* Wo    = (const float*)d_in[8];
  const float* bo    = (const float*)d_in[9];
  const float* gamma = (const float*)d_in[10];
  const float* beta  = (const float*)d_in[11];
  float* out = (float*)d_out;

  float *pq, *pk, *pv, *pctx, *po;
  unsigned* padjb;
  cudaGetSymbolAddress((void**)&pq,   g_q);
  cudaGetSymbolAddress((void**)&pk,   g_k);
  cudaGetSymbolAddress((void**)&pv,   g_v);
  cudaGetSymbolAddress((void**)&pctx, g_ctx);
  cudaGetSymbolAddress((void**)&po,   g_o);
  cudaGetSymbolAddress((void**)&padjb, g_adjb);

  pack_adj_kernel<<<SEQ*(SEQ/32)/256, 256>>>(adj, padjb);

  const dim3 gg(FD / 64, (BATCH * SEQ) / 64);
  gemm_bias_kernel<<<gg, 256>>>(x, Wq, bq, nullptr, pq);
  gemm_bias_kernel<<<gg, 256>>>(x, Wk, bk, nullptr, pk);
  gemm_bias_kernel<<<gg, 256>>>(x, Wv, bv, nullptr, pv);

  cudaFuncSetAttribute(attn_kernel, cudaFuncAttributeMaxDynamicSharedMemorySize,
                       SM_BYTES);
  const dim3 ga(SEQ / QT, NH, BATCH);
  attn_kernel<<<ga, 256, SM_BYTES>>>(pq, pk, pv, padjb, pctx);

  gemm_bias_kernel<<<gg, 256>>>(pctx, Wo, bo, x, po);
  ln_kernel<<<BATCH * SEQ, 256>>>(po, gamma, beta, out);
}

// round 4
// speedup vs baseline: 2.3580x; 2.2522x over previous
#include <cuda_runtime.h>
#include <cuda_bf16.h>
#include <cstdint>

#define BATCH 4
#define SEQ   2048
#define FD    256
#define NH    4
#define DH    64
#define CHK   256
#define NCHUNK 8

typedef unsigned long long ull;
typedef uint32_t u32;

// ---------------- device scratch ----------------
__device__ __nv_bfloat16 g_qh[BATCH*SEQ*FD];
__device__ __nv_bfloat16 g_ql[BATCH*SEQ*FD];
__device__ __nv_bfloat16 g_kh[BATCH*SEQ*FD];
__device__ __nv_bfloat16 g_kl[BATCH*SEQ*FD];
__device__ __nv_bfloat16 g_vh[BATCH*SEQ*FD];
__device__ __nv_bfloat16 g_vl[BATCH*SEQ*FD];
__device__ float g_ctx[BATCH*SEQ*FD];
__device__ float g_o[BATCH*SEQ*FD];
__device__ unsigned g_adjb[SEQ * (SEQ/32)];

// ---------------- helpers ----------------
__device__ __forceinline__ u32 smem_u32(const void* p) {
  u32 a; asm("{ .reg .u64 t; cvta.to.shared.u64 t, %1; cvt.u32.u64 %0, t; }"
             : "=r"(a) : "l"(p)); return a;
}
__device__ __forceinline__ float ex2f(float x) {
  float r; asm("ex2.approx.f32 %0, %1;" : "=f"(r) : "f"(x)); return r;
}
__device__ __forceinline__ float rcpf(float x) {
  float r; asm("rcp.approx.f32 %0, %1;" : "=f"(r) : "f"(x)); return r;
}
__device__ __forceinline__ void split1(float x, __nv_bfloat16& h, __nv_bfloat16& l) {
  h = __float2bfloat16_rn(x);
  l = __float2bfloat16_rn(x - __bfloat162float(h));
}
__device__ __forceinline__ u32 packbf(__nv_bfloat16 e0, __nv_bfloat16 e1) {
  return ((u32)__bfloat16_as_ushort(e1) << 16) | (u32)__bfloat16_as_ushort(e0);
}

// ldmatrix x4 (and transposed)
__device__ __forceinline__ void ldsm4(u32* r, u32 addr) {
  asm volatile("ldmatrix.sync.aligned.m8n8.x4.shared.b16 {%0,%1,%2,%3}, [%4];"
    : "=r"(r[0]), "=r"(r[1]), "=r"(r[2]), "=r"(r[3]) : "r"(addr));
}
__device__ __forceinline__ void ldsm4t(u32* r, u32 addr) {
  asm volatile("ldmatrix.sync.aligned.m8n8.x4.trans.shared.b16 {%0,%1,%2,%3}, [%4];"
    : "=r"(r[0]), "=r"(r[1]), "=r"(r[2]), "=r"(r[3]) : "r"(addr));
}
// mma m16n8k16 bf16 -> f32
__device__ __forceinline__ void mma16816(float* d, const u32* a, u32 b0, u32 b1) {
  asm volatile("mma.sync.aligned.m16n8k16.row.col.f32.bf16.bf16.f32 "
    "{%0,%1,%2,%3}, {%4,%5,%6,%7}, {%8,%9}, {%0,%1,%2,%3};"
    : "+f"(d[0]), "+f"(d[1]), "+f"(d[2]), "+f"(d[3])
    : "r"(a[0]), "r"(a[1]), "r"(a[2]), "r"(a[3]), "r"(b0), "r"(b1));
}

// ---------------- adjacency bit-pack ----------------
__global__ void pack_adj_kernel(const int* __restrict__ adj,
                                unsigned* __restrict__ adjb) {
  const int idx = blockIdx.x * 256 + threadIdx.x;
  const int4* p = (const int4*)(adj + (size_t)idx * 32);
  unsigned b = 0;
  #pragma unroll
  for (int u = 0; u < 8; u++) {
    int4 v = p[u];
    b |= (v.x != 0 ? 1u : 0u) << (u*4 + 0);
    b |= (v.y != 0 ? 1u : 0u) << (u*4 + 1);
    b |= (v.z != 0 ? 1u : 0u) << (u*4 + 2);
    b |= (v.w != 0 ? 1u : 0u) << (u*4 + 3);
  }
  adjb[idx] = b;
}

// ---------------- GEMM (f32x2 core). Epilogue: f32(+resid) OR split-bf16 planes ----------------
__device__ __forceinline__ ull pack2(float x, float y) {
  ull r; asm("mov.b64 %0, {%1, %2};" : "=l"(r) : "f"(x), "f"(y)); return r;
}
__device__ __forceinline__ float2 unpack2(ull v) {
  float2 r; asm("mov.b64 {%0, %1}, %2;" : "=f"(r.x), "=f"(r.y) : "l"(v)); return r;
}
__device__ __forceinline__ void ffma2(ull& d, ull a, ull b) {
  asm("fma.rn.f32x2 %0, %1, %2, %0;" : "+l"(d) : "l"(a), "l"(b));
}
union F2U { float2 f; ull u; };

__global__ void __launch_bounds__(256) gemm_bias_kernel(
    const float* __restrict__ A, const float* __restrict__ W,
    const float* __restrict__ bias, const float* __restrict__ resid,
    float* __restrict__ C,
    __nv_bfloat16* __restrict__ Ch, __nv_bfloat16* __restrict__ Cl,
    float oscale) {
  __shared__ __align__(16) float As[64][17];
  __shared__ __align__(16) float Wt[16][68];
  const int tid = threadIdx.x;
  const int tx = tid & 15, ty = tid >> 4;
  const int m0 = blockIdx.y * 64, n0 = blockIdx.x * 64;
  const int lrow = tid >> 2;
  const int lkb  = (tid & 3) * 4;

  ull acc2[4][2];
  #pragma unroll
  for (int i = 0; i < 4; i++) { acc2[i][0] = 0; acc2[i][1] = 0; }

  for (int k0 = 0; k0 < FD; k0 += 16) {
    float4 a4 = *(const float4*)&A[(size_t)(m0 + lrow) * FD + k0 + lkb];
    float4 w4 = *(const float4*)&W[(size_t)(n0 + lrow) * FD + k0 + lkb];
    As[lrow][lkb+0] = a4.x; As[lrow][lkb+1] = a4.y;
    As[lrow][lkb+2] = a4.z; As[lrow][lkb+3] = a4.w;
    Wt[lkb+0][lrow] = w4.x; Wt[lkb+1][lrow] = w4.y;
    Wt[lkb+2][lrow] = w4.z; Wt[lkb+3][lrow] = w4.w;
    __syncthreads();
    #pragma unroll
    for (int kk = 0; kk < 16; kk++) {
      F2U wv0, wv1;
      wv0.f = *(const float2*)&Wt[kk][tx*4];
      wv1.f = *(const float2*)&Wt[kk][tx*4 + 2];
      #pragma unroll
      for (int i = 0; i < 4; i++) {
        float a = As[ty*4 + i][kk];
        ull a2 = pack2(a, a);
        ffma2(acc2[i][0], wv0.u, a2);
        ffma2(acc2[i][1], wv1.u, a2);
      }
    }
    __syncthreads();
  }
  const int n = n0 + tx * 4;
  const float4 bb = *(const float4*)&bias[n];
  #pragma unroll
  for (int i = 0; i < 4; i++) {
    const int m = m0 + ty*4 + i;
    float2 x0 = unpack2(acc2[i][0]);
    float2 x1 = unpack2(acc2[i][1]);
    float4 o;
    o.x = x0.x + bb.x; o.y = x0.y + bb.y;
    o.z = x1.x + bb.z; o.w = x1.y + bb.w;
    if (Ch) {
      o.x *= oscale; o.y *= oscale; o.z *= oscale; o.w *= oscale;
      __nv_bfloat16 h0,h1,h2,h3,l0,l1,l2,l3;
      split1(o.x,h0,l0); split1(o.y,h1,l1); split1(o.z,h2,l2); split1(o.w,h3,l3);
      uint2 hw; hw.x = packbf(h0,h1); hw.y = packbf(h2,h3);
      uint2 lw; lw.x = packbf(l0,l1); lw.y = packbf(l2,l3);
      *(uint2*)&Ch[(size_t)m * FD + n] = hw;
      *(uint2*)&Cl[(size_t)m * FD + n] = lw;
    } else {
      if (resid) {
        float4 rr = *(const float4*)&resid[(size_t)m * FD + n];
        o.x += rr.x; o.y += rr.y; o.z += rr.z; o.w += rr.w;
      }
      *(float4*)&C[(size_t)m * FD + n] = o;
    }
  }
}

// ---------------- HMMA attention ----------------
// smem: bf16 planes, row pitch 72 elems = 144B (conflict-free ldmatrix)
#define PITCH 144
#define OFF_QH 0
#define OFF_QL (OFF_QH + 128*PITCH)      // 18432
#define OFF_KH (OFF_QL + 128*PITCH)      // 36864
#define OFF_KL (OFF_KH + 256*PITCH)      // 73728
#define OFF_VH (OFF_KL + 256*PITCH)      // 110592
#define OFF_VL (OFF_VH + 256*PITCH)      // 147456
#define OFF_ADJ (OFF_VL + 256*PITCH)     // 184320
#define SM_ATTN (OFF_ADJ + 128*8*4)      // 188416

__global__ void __launch_bounds__(256, 1) attn_hmma_kernel(
    const __nv_bfloat16* __restrict__ qh, const __nv_bfloat16* __restrict__ ql,
    const __nv_bfloat16* __restrict__ kh, const __nv_bfloat16* __restrict__ kl,
    const __nv_bfloat16* __restrict__ vh, const __nv_bfloat16* __restrict__ vl,
    const unsigned* __restrict__ adjb, float* __restrict__ ctx) {
  extern __shared__ __align__(16) char smem[];
  const u32 smb = smem_u32(smem);
  unsigned* adj_s = (unsigned*)(smem + OFF_ADJ);

  const int b  = blockIdx.z;
  const int h  = blockIdx.y;
  const int n0 = blockIdx.x * 128;
  const int t  = threadIdx.x;
  const int w  = t >> 5;
  const int l  = t & 31;
  const int gr = l >> 2, tg = l & 3;

  const float CLIP = 14.426950408889634f;       // 10*log2(e)
  const float ENEG = 4.5399929762484854e-05f;   // exp(-10)

  // ---- stage Q hi/lo [128 rows][64 bf16], pitch 144B ----
  {
    const char* gqh = (const char*)(qh + ((size_t)b*SEQ + n0)*FD + h*DH);
    const char* gql = (const char*)(ql + ((size_t)b*SEQ + n0)*FD + h*DH);
    #pragma unroll
    for (int i = 0; i < 4; i++) {
      int idx = t + i * 256;               // 1024 uint4 per plane
      int r = idx >> 3, c = idx & 7;
      *(uint4*)(smem + OFF_QH + r*PITCH + c*16) = *(const uint4*)(gqh + (size_t)r*512 + c*16);
      *(uint4*)(smem + OFF_QL + r*PITCH + c*16) = *(const uint4*)(gql + (size_t)r*512 + c*16);
    }
  }
  __syncthreads();

  // ---- Q fragments (live whole kernel): [ks 0..3][4 regs], hi + lo ----
  u32 qfh[4][4], qfl[4][4];
  {
    const u32 rowoff = (u32)(w*16 + (l & 15)) * PITCH;
    const u32 coloff = (u32)((l >> 4) * 8) * 2;
    #pragma unroll
    for (int ks = 0; ks < 4; ks++) {
      u32 a = smb + OFF_QH + rowoff + ks*32 + coloff;
      ldsm4(qfh[ks], a);
      ldsm4(qfl[ks], a + (OFF_QL - OFF_QH));
    }
  }

  float ctxa[8][4];
  #pragma unroll
  for (int i = 0; i < 8; i++)
    #pragma unroll
    for (int d = 0; d < 4; d++) ctxa[i][d] = 0.f;

  const char* gkh = (const char*)(kh + ((size_t)b*SEQ)*FD + h*DH);
  const char* gkl = (const char*)(kl + ((size_t)b*SEQ)*FD + h*DH);
  const char* gvh = (const char*)(vh + ((size_t)b*SEQ)*FD + h*DH);
  const char* gvl = (const char*)(vl + ((size_t)b*SEQ)*FD + h*DH);

  for (int j = 0; j < NCHUNK; ++j) {
    __syncthreads();
    // ---- stage K/V hi/lo chunk [256 rows][64 bf16] + adj bits ----
    {
      const size_t gbase = (size_t)(j * CHK) * 512;
      #pragma unroll
      for (int i = 0; i < 8; i++) {
        int idx = t + i * 256;             // 2048 uint4 per plane
        int r = idx >> 3, c = idx & 7;
        size_t go = gbase + (size_t)r*512 + c*16;
        u32 so = r*PITCH + c*16;
        *(uint4*)(smem + OFF_KH + so) = *(const uint4*)(gkh + go);
        *(uint4*)(smem + OFF_KL + so) = *(const uint4*)(gkl + go);
        *(uint4*)(smem + OFF_VH + so) = *(const uint4*)(gvh + go);
        *(uint4*)(smem + OFF_VL + so) = *(const uint4*)(gvl + go);
      }
      #pragma unroll
      for (int i = 0; i < 4; i++) {
        int idx = t + i * 256;             // 1024 words
        int row = idx >> 3, wi = idx & 7;
        adj_s[idx] = adjb[(size_t)(n0 + row) * (SEQ/32) + j * 8 + wi];
      }
    }
    __syncthreads();

    float rs0 = 0.f, rs1 = 0.f;
    float cU[8][4];
    #pragma unroll
    for (int i = 0; i < 8; i++)
      #pragma unroll
      for (int d = 0; d < 4; d++) cU[i][d] = 0.f;

    #pragma unroll
    for (int kb = 0; kb < 4; kb++) {
      const int key0 = kb * 64;
      // ---- S = Q.K^T over 64 keys (8 n-tiles), 3-split ----
      float S[8][4];
      #pragma unroll
      for (int i = 0; i < 8; i++)
        #pragma unroll
        for (int d = 0; d < 4; d++) S[i][d] = 0.f;

      const u32 lrow16 = (u32)(l & 15) * PITCH;
      const u32 chi = (u32)((l >> 4) * 8) * 2;
      #pragma unroll
      for (int ks = 0; ks < 4; ks++) {
        #pragma unroll
        for (int g = 0; g < 4; g++) {
          u32 a = smb + OFF_KH + (u32)(key0 + g*16)*PITCH + lrow16 + ks*32 + chi;
          u32 kf[4], kf2[4];
          ldsm4(kf,  a);
          ldsm4(kf2, a + (OFF_KL - OFF_KH));
          mma16816(S[2*g],   qfh[ks], kf[0],  kf[2]);
          mma16816(S[2*g+1], qfh[ks], kf[1],  kf[3]);
          mma16816(S[2*g],   qfh[ks], kf2[0], kf2[2]);
          mma16816(S[2*g+1], qfh[ks], kf2[1], kf2[3]);
          mma16816(S[2*g],   qfl[ks], kf[0],  kf[2]);
          mma16816(S[2*g+1], qfl[ks], kf[1],  kf[3]);
        }
      }

      // ---- mask + exp + pack P fragments ----
      const int lr0 = w*16 + gr;
      const u32 w00 = adj_s[lr0*8 + kb*2 + 0];
      const u32 w01 = adj_s[lr0*8 + kb*2 + 1];
      const u32 w10 = adj_s[(lr0+8)*8 + kb*2 + 0];
      const u32 w11 = adj_s[(lr0+8)*8 + kb*2 + 1];
      u32 Ph0[8], Ph1[8], Pl0[8], Pl1[8];
      #pragma unroll
      for (int nt = 0; nt < 8; nt++) {
        const u32 wr0 = (nt < 4) ? w00 : w10 * 0 + w00 * 0 + w00;  // placeholder avoided below
        (void)wr0;
        const u32 a0w = (nt < 4) ? w00 : w01;
        const u32 a1w = (nt < 4) ? w10 : w11;
        const int bit = (nt & 3) * 8 + 2 * tg;
        float x;
        x = fminf(fmaxf(S[nt][0], -CLIP), CLIP);
        float e00 = ((a0w >> bit) & 1u)     ? ex2f(x) : ENEG;
        x = fminf(fmaxf(S[nt][1], -CLIP), CLIP);
        float e01 = ((a0w >> (bit+1)) & 1u) ? ex2f(x) : ENEG;
        x = fminf(fmaxf(S[nt][2], -CLIP), CLIP);
        float e10 = ((a1w >> bit) & 1u)     ? ex2f(x) : ENEG;
        x = fminf(fmaxf(S[nt][3], -CLIP), CLIP);
        float e11 = ((a1w >> (bit+1)) & 1u) ? ex2f(x) : ENEG;
        rs0 += e00 + e01;
        rs1 += e10 + e11;
        __nv_bfloat16 h0,l0,h1,l1,h2,l2,h3,l3;
        split1(e00,h0,l0); split1(e01,h1,l1);
        split1(e10,h2,l2); split1(e11,h3,l3);
        Ph0[nt] = packbf(h0,h1); Pl0[nt] = packbf(l0,l1);
        Ph1[nt] = packbf(h2,h3); Pl1[nt] = packbf(l2,l3);
      }

      // ---- ctxU += P.V (3-split) ----
      #pragma unroll
      for (int kt = 0; kt < 4; kt++) {
        u32 Ah[4] = { Ph0[2*kt], Ph1[2*kt], Ph0[2*kt+1], Ph1[2*kt+1] };
        u32 Al[4] = { Pl0[2*kt], Pl1[2*kt], Pl0[2*kt+1], Pl1[2*kt+1] };
        const u32 vrow = (u32)(key0 + kt*16) * PITCH + lrow16;
        #pragma unroll
        for (int dg = 0; dg < 4; dg++) {
          u32 a = smb + OFF_VH + vrow + dg*32 + chi;
          u32 vf[4], vf2[4];
          ldsm4t(vf,  a);
          ldsm4t(vf2, a + (OFF_VL - OFF_VH));
          mma16816(cU[2*dg],   Ah, vf[0],  vf[1]);
          mma16816(cU[2*dg+1], Ah, vf[2],  vf[3]);
          mma16816(cU[2*dg],   Ah, vf2[0], vf2[1]);
          mma16816(cU[2*dg+1], Ah, vf2[2], vf2[3]);
          mma16816(cU[2*dg],   Al, vf[0],  vf[1]);
          mma16816(cU[2*dg+1], Al, vf[2],  vf[3]);
        }
      }
    }

    // ---- per-chunk softmax normalization folded into accumulate ----
    float t0 = rs0;
    t0 += __shfl_xor_sync(0xFFFFFFFFu, t0, 1);
    t0 += __shfl_xor_sync(0xFFFFFFFFu, t0, 2);
    float t1 = rs1;
    t1 += __shfl_xor_sync(0xFFFFFFFFu, t1, 1);
    t1 += __shfl_xor_sync(0xFFFFFFFFu, t1, 2);
    const float r0 = rcpf(t0), r1 = rcpf(t1);
    #pragma unroll
    for (int i = 0; i < 8; i++) {
      ctxa[i][0] += cU[i][0] * r0;
      ctxa[i][1] += cU[i][1] * r0;
      ctxa[i][2] += cU[i][2] * r1;
      ctxa[i][3] += cU[i][3] * r1;
    }
  }

  // ---- store ctx ----
  {
    const int row0 = n0 + w*16 + gr;
    float* cg0 = ctx + ((size_t)b*SEQ + row0)*FD + h*DH;
    float* cg1 = cg0 + (size_t)8*FD;
    #pragma unroll
    for (int nt = 0; nt < 8; nt++) {
      float2 o0; o0.x = ctxa[nt][0]; o0.y = ctxa[nt][1];
      float2 o1; o1.x = ctxa[nt][2]; o1.y = ctxa[nt][3];
      *(float2*)(cg0 + nt*8 + 2*tg) = o0;
      *(float2*)(cg1 + nt*8 + 2*tg) = o1;
    }
  }
}

// ---------------- LayerNorm ----------------
__global__ void ln_kernel(const float* __restrict__ o,
                          const float* __restrict__ gamma,
                          const float* __restrict__ beta,
                          float* __restrict__ out) {
  const int row = blockIdx.x;
  const int t = threadIdx.x;
  const int w = t >> 5, l = t & 31;
  const float val = o[(size_t)row * FD + t];

  float s1 = val, s2 = val * val;
  #pragma unroll
  for (int off = 16; off > 0; off >>= 1) {
    s1 += __shfl_xor_sync(0xFFFFFFFFu, s1, off);
    s2 += __shfl_xor_sync(0xFFFFFFFFu, s2, off);
  }
  __shared__ float rs1[8], rs2[8];
  __shared__ float mu_s, rstd_s;
  if (l == 0) { rs1[w] = s1; rs2[w] = s2; }
  __syncthreads();
  if (t == 0) {
    float S1 = 0.f, S2 = 0.f;
    #pragma unroll
    for (int i = 0; i < 8; i++) { S1 += rs1[i]; S2 += rs2[i]; }
    const float mu = S1 * (1.f / FD);
    const float var = S2 * (1.f / FD) - mu * mu;
    mu_s = mu;
    rstd_s = rsqrtf(var + 1e-5f);
  }
  __syncthreads();
  out[(size_t)row * FD + t] = (val - mu_s) * rstd_s * gamma[t] + beta[t];
}

// ---------------- launch ----------------
extern "C" void kernel_launch(void* const* d_in, const int* in_sizes, int n_in,
                              void* d_out, int out_size) {
  (void)in_sizes; (void)n_in; (void)out_size;
  const float* x     = (const float*)d_in[0];
  const int*   adj   = (const int*)  d_in[1];
  const float* Wq    = (const float*)d_in[2];
  const float* bq    = (const float*)d_in[3];
  const float* Wk    = (const float*)d_in[4];
  const float* bk    = (const float*)d_in[5];
  const float* Wv    = (const float*)d_in[6];
  const float* bv    = (const float*)d_in[7];
  const float* Wo    = (const float*)d_in[8];
  const float* bo    = (const float*)d_in[9];
  const float* gamma = (const float*)d_in[10];
  const float* beta  = (const float*)d_in[11];
  float* out = (float*)d_out;

  __nv_bfloat16 *pqh, *pql, *pkh, *pkl, *pvh, *pvl;
  float *pctx, *po;
  unsigned* padjb;
  cudaGetSymbolAddress((void**)&pqh, g_qh);
  cudaGetSymbolAddress((void**)&pql, g_ql);
  cudaGetSymbolAddress((void**)&pkh, g_kh);
  cudaGetSymbolAddress((void**)&pkl, g_kl);
  cudaGetSymbolAddress((void**)&pvh, g_vh);
  cudaGetSymbolAddress((void**)&pvl, g_vl);
  cudaGetSymbolAddress((void**)&pctx, g_ctx);
  cudaGetSymbolAddress((void**)&po,   g_o);
  cudaGetSymbolAddress((void**)&padjb, g_adjb);

  pack_adj_kernel<<<SEQ*(SEQ/32)/256, 256>>>(adj, padjb);

  const float QS = 0.18033688011112042f;   // 0.125 * log2(e)
  const dim3 gg(FD / 64, (BATCH * SEQ) / 64);
  gemm_bias_kernel<<<gg, 256>>>(x, Wq, bq, nullptr, nullptr, pqh, pql, QS);
  gemm_bias_kernel<<<gg, 256>>>(x, Wk, bk, nullptr, nullptr, pkh, pkl, 1.f);
  gemm_bias_kernel<<<gg, 256>>>(x, Wv, bv, nullptr, nullptr, pvh, pvl, 1.f);

  cudaFuncSetAttribute(attn_hmma_kernel, cudaFuncAttributeMaxDynamicSharedMemorySize,
                       SM_ATTN);
  const dim3 ga(SEQ / 128, NH, BATCH);
  attn_hmma_kernel<<<ga, 256, SM_ATTN>>>(pqh, pql, pkh, pkl, pvh, pvl, padjb, pctx);

  gemm_bias_kernel<<<gg, 256>>>(pctx, Wo, bo, x, po, nullptr, nullptr, 1.f);
  ln_kernel<<<BATCH * SEQ, 256>>>(po, gamma, beta, out);
}

// round 5
// speedup vs baseline: 2.5925x; 1.0995x over previous
#include <cuda_runtime.h>
#include <cuda_bf16.h>
#include <cstdint>

#define BATCH 4
#define SEQ   2048
#define FD    256
#define NH    4
#define DH    64
#define CHK   256
#define NCHUNK 8

typedef unsigned long long ull;
typedef uint32_t u32;

// ---------------- device scratch ----------------
__device__ __nv_bfloat16 g_qh[BATCH*SEQ*FD];
__device__ __nv_bfloat16 g_ql[BATCH*SEQ*FD];
__device__ __nv_bfloat16 g_kh[BATCH*SEQ*FD];
__device__ __nv_bfloat16 g_kl[BATCH*SEQ*FD];
__device__ __nv_bfloat16 g_vh[BATCH*SEQ*FD];
__device__ __nv_bfloat16 g_vl[BATCH*SEQ*FD];
__device__ float g_ctx[BATCH*SEQ*FD];
__device__ float g_o[BATCH*SEQ*FD];
__device__ unsigned g_adjb[SEQ * (SEQ/32)];

// ---------------- helpers ----------------
__device__ __forceinline__ u32 smem_u32(const void* p) {
  u32 a; asm("{ .reg .u64 t; cvta.to.shared.u64 t, %1; cvt.u32.u64 %0, t; }"
             : "=r"(a) : "l"(p)); return a;
}
__device__ __forceinline__ float ex2f(float x) {
  float r; asm("ex2.approx.f32 %0, %1;" : "=f"(r) : "f"(x)); return r;
}
__device__ __forceinline__ float rcpf(float x) {
  float r; asm("rcp.approx.f32 %0, %1;" : "=f"(r) : "f"(x)); return r;
}
__device__ __forceinline__ void split1(float x, __nv_bfloat16& h, __nv_bfloat16& l) {
  h = __float2bfloat16_rn(x);
  l = __float2bfloat16_rn(x - __bfloat162float(h));
}
__device__ __forceinline__ u32 packbf(__nv_bfloat16 e0, __nv_bfloat16 e1) {
  return ((u32)__bfloat16_as_ushort(e1) << 16) | (u32)__bfloat16_as_ushort(e0);
}
__device__ __forceinline__ ull pack2(float x, float y) {
  ull r; asm("mov.b64 %0, {%1, %2};" : "=l"(r) : "f"(x), "f"(y)); return r;
}
__device__ __forceinline__ float2 unpack2(ull v) {
  float2 r; asm("mov.b64 {%0, %1}, %2;" : "=f"(r.x), "=f"(r.y) : "l"(v)); return r;
}
__device__ __forceinline__ void ffma2(ull& d, ull a, ull b) {
  asm("fma.rn.f32x2 %0, %1, %2, %0;" : "+l"(d) : "l"(a), "l"(b));
}
union F2U { float2 f; ull u; };

// ldmatrix x4 (and transposed)
__device__ __forceinline__ void ldsm4(u32* r, u32 addr) {
  asm volatile("ldmatrix.sync.aligned.m8n8.x4.shared.b16 {%0,%1,%2,%3}, [%4];"
    : "=r"(r[0]), "=r"(r[1]), "=r"(r[2]), "=r"(r[3]) : "r"(addr));
}
__device__ __forceinline__ void ldsm4t(u32* r, u32 addr) {
  asm volatile("ldmatrix.sync.aligned.m8n8.x4.trans.shared.b16 {%0,%1,%2,%3}, [%4];"
    : "=r"(r[0]), "=r"(r[1]), "=r"(r[2]), "=r"(r[3]) : "r"(addr));
}
// mma m16n8k16 bf16 -> f32
__device__ __forceinline__ void mma16816(float* d, const u32* a, u32 b0, u32 b1) {
  asm volatile("mma.sync.aligned.m16n8k16.row.col.f32.bf16.bf16.f32 "
    "{%0,%1,%2,%3}, {%4,%5,%6,%7}, {%8,%9}, {%0,%1,%2,%3};"
    : "+f"(d[0]), "+f"(d[1]), "+f"(d[2]), "+f"(d[3])
    : "r"(a[0]), "r"(a[1]), "r"(a[2]), "r"(a[3]), "r"(b0), "r"(b1));
}

// ---------------- adjacency bit-pack ----------------
__global__ void pack_adj_kernel(const int* __restrict__ adj,
                                unsigned* __restrict__ adjb) {
  const int idx = blockIdx.x * 256 + threadIdx.x;
  const int4* p = (const int4*)(adj + (size_t)idx * 32);
  unsigned b = 0;
  #pragma unroll
  for (int u = 0; u < 8; u++) {
    int4 v = p[u];
    b |= (v.x != 0 ? 1u : 0u) << (u*4 + 0);
    b |= (v.y != 0 ? 1u : 0u) << (u*4 + 1);
    b |= (v.z != 0 ? 1u : 0u) << (u*4 + 2);
    b |= (v.w != 0 ? 1u : 0u) << (u*4 + 3);
  }
  adjb[idx] = b;
}

// ---------------- FFMA2 GEMM core: 64x256 tile, 128 threads ----------------
// thread (tx 0..15, ty 0..7): rows m0+ty+8i (i<8), col pairs 32jp+2tx (jp<8)
#define AS_PITCH 20
#define WT_PITCH 266
#define AS_WORDS (64*AS_PITCH)     // 1280
#define WT_WORDS (16*WT_PITCH)     // 4256

template<bool SPLIT>
__device__ __forceinline__ void gemm_core(
    const float* __restrict__ A, const float* __restrict__ W,
    const float* __restrict__ bias, const float* __restrict__ resid,
    float* __restrict__ Cf,
    __nv_bfloat16* __restrict__ Ch, __nv_bfloat16* __restrict__ Cl,
    float oscale, int m0, float* As, float* Wt) {
  const int t  = threadIdx.x;
  const int tx = t & 15, ty = t >> 4;

  ull acc[8][8];
  #pragma unroll
  for (int i = 0; i < 8; i++)
    #pragma unroll
    for (int jp = 0; jp < 8; jp++) acc[i][jp] = 0;

  float4 la[2], lw[8];
  const int r_a  = (t + 0) >> 2;           // used with idx pattern below
  (void)r_a;

  // ldg tile kt
  auto LDG = [&](int kt) {
    const float* ap = A + (size_t)m0 * FD + kt * 16;
    #pragma unroll
    for (int i = 0; i < 2; i++) {
      int idx = t + i * 128; int r = idx >> 2, kq = (idx & 3) << 2;
      la[i] = *(const float4*)&ap[(size_t)r * FD + kq];
    }
    const float* wp = W + kt * 16;
    #pragma unroll
    for (int i = 0; i < 8; i++) {
      int idx = t + i * 128; int n = idx >> 2, kq = (idx & 3) << 2;
      lw[i] = *(const float4*)&wp[(size_t)n * FD + kq];
    }
  };
  auto STS = [&](int buf) {
    float* as = As + buf * AS_WORDS;
    #pragma unroll
    for (int i = 0; i < 2; i++) {
      int idx = t + i * 128; int r = idx >> 2, kq = (idx & 3) << 2;
      *(float4*)&as[r * AS_PITCH + kq] = la[i];
    }
    float* wt = Wt + buf * WT_WORDS;
    #pragma unroll
    for (int i = 0; i < 8; i++) {
      int idx = t + i * 128; int n = idx >> 2, kq = (idx & 3) << 2;
      wt[(kq + 0) * WT_PITCH + n] = lw[i].x;
      wt[(kq + 1) * WT_PITCH + n] = lw[i].y;
      wt[(kq + 2) * WT_PITCH + n] = lw[i].z;
      wt[(kq + 3) * WT_PITCH + n] = lw[i].w;
    }
  };

  LDG(0);
  STS(0);
  __syncthreads();

  int buf = 0;
  for (int kt = 0; kt < 16; kt++) {
    if (kt < 15) LDG(kt + 1);
    const float* as = As + buf * AS_WORDS;
    const float* wt = Wt + buf * WT_WORDS + 2 * tx;
    #pragma unroll
    for (int kk = 0; kk < 16; kk++) {
      F2U wv[8];
      #pragma unroll
      for (int jp = 0; jp < 8; jp++)
        wv[jp].f = *(const float2*)&wt[kk * WT_PITCH + 32 * jp];
      ull a2[8];
      #pragma unroll
      for (int i = 0; i < 8; i++) {
        float a = as[(ty + 8 * i) * AS_PITCH + kk];
        a2[i] = pack2(a, a);
      }
      #pragma unroll
      for (int i = 0; i < 8; i++)
        #pragma unroll
        for (int jp = 0; jp < 8; jp++) ffma2(acc[i][jp], wv[jp].u, a2[i]);
    }
    if (kt < 15) {
      STS(buf ^ 1);
      __syncthreads();
      buf ^= 1;
    }
  }

  // epilogue
  #pragma unroll
  for (int jp = 0; jp < 8; jp++) {
    const int n = 32 * jp + 2 * tx;
    const float2 bb = *(const float2*)&bias[n];
    #pragma unroll
    for (int i = 0; i < 8; i++) {
      const int m = m0 + ty + 8 * i;
      float2 c = unpack2(acc[i][jp]);
      c.x += bb.x; c.y += bb.y;
      if (SPLIT) {
        c.x *= oscale; c.y *= oscale;
        __nv_bfloat16 h0, l0, h1, l1;
        split1(c.x, h0, l0); split1(c.y, h1, l1);
        *(u32*)&Ch[(size_t)m * FD + n] = packbf(h0, h1);
        *(u32*)&Cl[(size_t)m * FD + n] = packbf(l0, l1);
      } else {
        float2 rr = *(const float2*)&resid[(size_t)m * FD + n];
        c.x += rr.x; c.y += rr.y;
        *(float2*)&Cf[(size_t)m * FD + n] = c;
      }
    }
  }
}

// QKV fused: blockIdx.y selects projection; outputs split bf16 planes
__global__ void __launch_bounds__(128) qkv_gemm_kernel(
    const float* __restrict__ x,
    const float* __restrict__ Wq, const float* __restrict__ bq,
    const float* __restrict__ Wk, const float* __restrict__ bk,
    const float* __restrict__ Wv, const float* __restrict__ bv,
    __nv_bfloat16* __restrict__ qh, __nv_bfloat16* __restrict__ ql,
    __nv_bfloat16* __restrict__ kh, __nv_bfloat16* __restrict__ kl,
    __nv_bfloat16* __restrict__ vh, __nv_bfloat16* __restrict__ vl,
    float qscale) {
  __shared__ __align__(16) float As[2 * AS_WORDS];
  __shared__ __align__(16) float Wt[2 * WT_WORDS];
  const int y = blockIdx.y;
  const float* W = (y == 0) ? Wq : (y == 1) ? Wk : Wv;
  const float* bias = (y == 0) ? bq : (y == 1) ? bk : bv;
  __nv_bfloat16* Ch = (y == 0) ? qh : (y == 1) ? kh : vh;
  __nv_bfloat16* Cl = (y == 0) ? ql : (y == 1) ? kl : vl;
  const float sc = (y == 0) ? qscale : 1.f;
  gemm_core<true>(x, W, bias, nullptr, nullptr, Ch, Cl, sc,
                  blockIdx.x * 64, As, Wt);
}

// O projection: fp32 + residual
__global__ void __launch_bounds__(128) o_gemm_kernel(
    const float* __restrict__ ctx, const float* __restrict__ Wo,
    const float* __restrict__ bo, const float* __restrict__ x,
    float* __restrict__ o) {
  __shared__ __align__(16) float As[2 * AS_WORDS];
  __shared__ __align__(16) float Wt[2 * WT_WORDS];
  gemm_core<false>(ctx, Wo, bo, x, o, nullptr, nullptr, 1.f,
                   blockIdx.x * 64, As, Wt);
}

// ---------------- HMMA attention (unchanged from R4) ----------------
#define PITCH 144
#define OFF_QH 0
#define OFF_QL (OFF_QH + 128*PITCH)
#define OFF_KH (OFF_QL + 128*PITCH)
#define OFF_KL (OFF_KH + 256*PITCH)
#define OFF_VH (OFF_KL + 256*PITCH)
#define OFF_VL (OFF_VH + 256*PITCH)
#define OFF_ADJ (OFF_VL + 256*PITCH)
#define SM_ATTN (OFF_ADJ + 128*8*4)

__global__ void __launch_bounds__(256, 1) attn_hmma_kernel(
    const __nv_bfloat16* __restrict__ qh, const __nv_bfloat16* __restrict__ ql,
    const __nv_bfloat16* __restrict__ kh, const __nv_bfloat16* __restrict__ kl,
    const __nv_bfloat16* __restrict__ vh, const __nv_bfloat16* __restrict__ vl,
    const unsigned* __restrict__ adjb, float* __restrict__ ctx) {
  extern __shared__ __align__(16) char smem[];
  const u32 smb = smem_u32(smem);
  unsigned* adj_s = (unsigned*)(smem + OFF_ADJ);

  const int b  = blockIdx.z;
  const int h  = blockIdx.y;
  const int n0 = blockIdx.x * 128;
  const int t  = threadIdx.x;
  const int w  = t >> 5;
  const int l  = t & 31;
  const int gr = l >> 2, tg = l & 3;

  const float CLIP = 14.426950408889634f;
  const float ENEG = 4.5399929762484854e-05f;

  {
    const char* gqh = (const char*)(qh + ((size_t)b*SEQ + n0)*FD + h*DH);
    const char* gql = (const char*)(ql + ((size_t)b*SEQ + n0)*FD + h*DH);
    #pragma unroll
    for (int i = 0; i < 4; i++) {
      int idx = t + i * 256;
      int r = idx >> 3, c = idx & 7;
      *(uint4*)(smem + OFF_QH + r*PITCH + c*16) = *(const uint4*)(gqh + (size_t)r*512 + c*16);
      *(uint4*)(smem + OFF_QL + r*PITCH + c*16) = *(const uint4*)(gql + (size_t)r*512 + c*16);
    }
  }
  __syncthreads();

  u32 qfh[4][4], qfl[4][4];
  {
    const u32 rowoff = (u32)(w*16 + (l & 15)) * PITCH;
    const u32 coloff = (u32)((l >> 4) * 8) * 2;
    #pragma unroll
    for (int ks = 0; ks < 4; ks++) {
      u32 a = smb + OFF_QH + rowoff + ks*32 + coloff;
      ldsm4(qfh[ks], a);
      ldsm4(qfl[ks], a + (OFF_QL - OFF_QH));
    }
  }

  float ctxa[8][4];
  #pragma unroll
  for (int i = 0; i < 8; i++)
    #pragma unroll
    for (int d = 0; d < 4; d++) ctxa[i][d] = 0.f;

  const char* gkh = (const char*)(kh + ((size_t)b*SEQ)*FD + h*DH);
  const char* gkl = (const char*)(kl + ((size_t)b*SEQ)*FD + h*DH);
  const char* gvh = (const char*)(vh + ((size_t)b*SEQ)*FD + h*DH);
  const char* gvl = (const char*)(vl + ((size_t)b*SEQ)*FD + h*DH);

  for (int j = 0; j < NCHUNK; ++j) {
    __syncthreads();
    {
      const size_t gbase = (size_t)(j * CHK) * 512;
      #pragma unroll
      for (int i = 0; i < 8; i++) {
        int idx = t + i * 256;
        int r = idx >> 3, c = idx & 7;
        size_t go = gbase + (size_t)r*512 + c*16;
        u32 so = r*PITCH + c*16;
        *(uint4*)(smem + OFF_KH + so) = *(const uint4*)(gkh + go);
        *(uint4*)(smem + OFF_KL + so) = *(const uint4*)(gkl + go);
        *(uint4*)(smem + OFF_VH + so) = *(const uint4*)(gvh + go);
        *(uint4*)(smem + OFF_VL + so) = *(const uint4*)(gvl + go);
      }
      #pragma unroll
      for (int i = 0; i < 4; i++) {
        int idx = t + i * 256;
        int row = idx >> 3, wi = idx & 7;
        adj_s[idx] = adjb[(size_t)(n0 + row) * (SEQ/32) + j * 8 + wi];
      }
    }
    __syncthreads();

    float rs0 = 0.f, rs1 = 0.f;
    float cU[8][4];
    #pragma unroll
    for (int i = 0; i < 8; i++)
      #pragma unroll
      for (int d = 0; d < 4; d++) cU[i][d] = 0.f;

    #pragma unroll
    for (int kb = 0; kb < 4; kb++) {
      const int key0 = kb * 64;
      float S[8][4];
      #pragma unroll
      for (int i = 0; i < 8; i++)
        #pragma unroll
        for (int d = 0; d < 4; d++) S[i][d] = 0.f;

      const u32 lrow16 = (u32)(l & 15) * PITCH;
      const u32 chi = (u32)((l >> 4) * 8) * 2;
      #pragma unroll
      for (int ks = 0; ks < 4; ks++) {
        #pragma unroll
        for (int g = 0; g < 4; g++) {
          u32 a = smb + OFF_KH + (u32)(key0 + g*16)*PITCH + lrow16 + ks*32 + chi;
          u32 kf[4], kf2[4];
          ldsm4(kf,  a);
          ldsm4(kf2, a + (OFF_KL - OFF_KH));
          mma16816(S[2*g],   qfh[ks], kf[0],  kf[2]);
          mma16816(S[2*g+1], qfh[ks], kf[1],  kf[3]);
          mma16816(S[2*g],   qfh[ks], kf2[0], kf2[2]);
          mma16816(S[2*g+1], qfh[ks], kf2[1], kf2[3]);
          mma16816(S[2*g],   qfl[ks], kf[0],  kf[2]);
          mma16816(S[2*g+1], qfl[ks], kf[1],  kf[3]);
        }
      }

      const int lr0 = w*16 + gr;
      const u32 w00 = adj_s[lr0*8 + kb*2 + 0];
      const u32 w01 = adj_s[lr0*8 + kb*2 + 1];
      const u32 w10 = adj_s[(lr0+8)*8 + kb*2 + 0];
      const u32 w11 = adj_s[(lr0+8)*8 + kb*2 + 1];
      u32 Ph0[8], Ph1[8], Pl0[8], Pl1[8];
      #pragma unroll
      for (int nt = 0; nt < 8; nt++) {
        const u32 a0w = (nt < 4) ? w00 : w01;
        const u32 a1w = (nt < 4) ? w10 : w11;
        const int bit = (nt & 3) * 8 + 2 * tg;
        float x;
        x = fminf(fmaxf(S[nt][0], -CLIP), CLIP);
        float e00 = ((a0w >> bit) & 1u)     ? ex2f(x) : ENEG;
        x = fminf(fmaxf(S[nt][1], -CLIP), CLIP);
        float e01 = ((a0w >> (bit+1)) & 1u) ? ex2f(x) : ENEG;
        x = fminf(fmaxf(S[nt][2], -CLIP), CLIP);
        float e10 = ((a1w >> bit) & 1u)     ? ex2f(x) : ENEG;
        x = fminf(fmaxf(S[nt][3], -CLIP), CLIP);
        float e11 = ((a1w >> (bit+1)) & 1u) ? ex2f(x) : ENEG;
        rs0 += e00 + e01;
        rs1 += e10 + e11;
        __nv_bfloat16 h0,l0,h1,l1,h2,l2,h3,l3;
        split1(e00,h0,l0); split1(e01,h1,l1);
        split1(e10,h2,l2); split1(e11,h3,l3);
        Ph0[nt] = packbf(h0,h1); Pl0[nt] = packbf(l0,l1);
        Ph1[nt] = packbf(h2,h3); Pl1[nt] = packbf(l2,l3);
      }

      #pragma unroll
      for (int kt = 0; kt < 4; kt++) {
        u32 Ah[4] = { Ph0[2*kt], Ph1[2*kt], Ph0[2*kt+1], Ph1[2*kt+1] };
        u32 Al[4] = { Pl0[2*kt], Pl1[2*kt], Pl0[2*kt+1], Pl1[2*kt+1] };
        const u32 vrow = (u32)(key0 + kt*16) * PITCH + lrow16;
        #pragma unroll
        for (int dg = 0; dg < 4; dg++) {
          u32 a = smb + OFF_VH + vrow + dg*32 + chi;
          u32 vf[4], vf2[4];
          ldsm4t(vf,  a);
          ldsm4t(vf2, a + (OFF_VL - OFF_VH));
          mma16816(cU[2*dg],   Ah, vf[0],  vf[1]);
          mma16816(cU[2*dg+1], Ah, vf[2],  vf[3]);
          mma16816(cU[2*dg],   Ah, vf2[0], vf2[1]);
          mma16816(cU[2*dg+1], Ah, vf2[2], vf2[3]);
          mma16816(cU[2*dg],   Al, vf[0],  vf[1]);
          mma16816(cU[2*dg+1], Al, vf[2],  vf[3]);
        }
      }
    }

    float t0 = rs0;
    t0 += __shfl_xor_sync(0xFFFFFFFFu, t0, 1);
    t0 += __shfl_xor_sync(0xFFFFFFFFu, t0, 2);
    float t1 = rs1;
    t1 += __shfl_xor_sync(0xFFFFFFFFu, t1, 1);
    t1 += __shfl_xor_sync(0xFFFFFFFFu, t1, 2);
    const float r0 = rcpf(t0), r1 = rcpf(t1);
    #pragma unroll
    for (int i = 0; i < 8; i++) {
      ctxa[i][0] += cU[i][0] * r0;
      ctxa[i][1] += cU[i][1] * r0;
      ctxa[i][2] += cU[i][2] * r1;
      ctxa[i][3] += cU[i][3] * r1;
    }
  }

  {
    const int row0 = n0 + w*16 + gr;
    float* cg0 = ctx + ((size_t)b*SEQ + row0)*FD + h*DH;
    float* cg1 = cg0 + (size_t)8*FD;
    #pragma unroll
    for (int nt = 0; nt < 8; nt++) {
      float2 o0; o0.x = ctxa[nt][0]; o0.y = ctxa[nt][1];
      float2 o1; o1.x = ctxa[nt][2]; o1.y = ctxa[nt][3];
      *(float2*)(cg0 + nt*8 + 2*tg) = o0;
      *(float2*)(cg1 + nt*8 + 2*tg) = o1;
    }
  }
}

// ---------------- LayerNorm ----------------
__global__ void ln_kernel(const float* __restrict__ o,
                          const float* __restrict__ gamma,
                          const float* __restrict__ beta,
                          float* __restrict__ out) {
  const int row = blockIdx.x;
  const int t = threadIdx.x;
  const int w = t >> 5, l = t & 31;
  const float val = o[(size_t)row * FD + t];

  float s1 = val, s2 = val * val;
  #pragma unroll
  for (int off = 16; off > 0; off >>= 1) {
    s1 += __shfl_xor_sync(0xFFFFFFFFu, s1, off);
    s2 += __shfl_xor_sync(0xFFFFFFFFu, s2, off);
  }
  __shared__ float rs1[8], rs2[8];
  __shared__ float mu_s, rstd_s;
  if (l == 0) { rs1[w] = s1; rs2[w] = s2; }
  __syncthreads();
  if (t == 0) {
    float S1 = 0.f, S2 = 0.f;
    #pragma unroll
    for (int i = 0; i < 8; i++) { S1 += rs1[i]; S2 += rs2[i]; }
    const float mu = S1 * (1.f / FD);
    const float var = S2 * (1.f / FD) - mu * mu;
    mu_s = mu;
    rstd_s = rsqrtf(var + 1e-5f);
  }
  __syncthreads();
  out[(size_t)row * FD + t] = (val - mu_s) * rstd_s * gamma[t] + beta[t];
}

// ---------------- launch ----------------
extern "C" void kernel_launch(void* const* d_in, const int* in_sizes, int n_in,
                              void* d_out, int out_size) {
  (void)in_sizes; (void)n_in; (void)out_size;
  const float* x     = (const float*)d_in[0];
  const int*   adj   = (const int*)  d_in[1];
  const float* Wq    = (const float*)d_in[2];
  const float* bq    = (const float*)d_in[3];
  const float* Wk    = (const float*)d_in[4];
  const float* bk    = (const float*)d_in[5];
  const float* Wv    = (const float*)d_in[6];
  const float* bv    = (const float*)d_in[7];
  const float* Wo    = (const float*)d_in[8];
  const float* bo    = (const float*)d_in[9];
  const float* gamma = (const float*)d_in[10];
  const float* beta  = (const float*)d_in[11];
  float* out = (float*)d_out;

  __nv_bfloat16 *pqh, *pql, *pkh, *pkl, *pvh, *pvl;
  float *pctx, *po;
  unsigned* padjb;
  cudaGetSymbolAddress((void**)&pqh, g_qh);
  cudaGetSymbolAddress((void**)&pql, g_ql);
  cudaGetSymbolAddress((void**)&pkh, g_kh);
  cudaGetSymbolAddress((void**)&pkl, g_kl);
  cudaGetSymbolAddress((void**)&pvh, g_vh);
  cudaGetSymbolAddress((void**)&pvl, g_vl);
  cudaGetSymbolAddress((void**)&pctx, g_ctx);
  cudaGetSymbolAddress((void**)&po,   g_o);
  cudaGetSymbolAddress((void**)&padjb, g_adjb);

  pack_adj_kernel<<<SEQ*(SEQ/32)/256, 256>>>(adj, padjb);

  const float QS = 0.18033688011112042f;   // 0.125 * log2(e)
  qkv_gemm_kernel<<<dim3((BATCH*SEQ)/64, 3), 128>>>(
      x, Wq, bq, Wk, bk, Wv, bv, pqh, pql, pkh, pkl, pvh, pvl, QS);

  cudaFuncSetAttribute(attn_hmma_kernel, cudaFuncAttributeMaxDynamicSharedMemorySize,
                       SM_ATTN);
  const dim3 ga(SEQ / 128, NH, BATCH);
  attn_hmma_kernel<<<ga, 256, SM_ATTN>>>(pqh, pql, pkh, pkl, pvh, pvl, padjb, pctx);

  o_gemm_kernel<<<(BATCH*SEQ)/64, 128>>>(pctx, Wo, bo, x, po);
  ln_kernel<<<BATCH * SEQ, 256>>>(po, gamma, beta, out);
}

// round 6
// speedup vs baseline: 3.0291x; 1.1684x over previous
#include <cuda_runtime.h>
#include <cuda_bf16.h>
#include <cstdint>

#define BATCH 4
#define SEQ   2048
#define FD    256
#define NH    4
#define DH    64
#define CHK   256
#define NCHUNK 8

typedef unsigned long long ull;
typedef uint32_t u32;

// ---------------- device scratch ----------------
__device__ __nv_bfloat16 g_xh[BATCH*SEQ*FD];
__device__ __nv_bfloat16 g_xl[BATCH*SEQ*FD];
__device__ __nv_bfloat16 g_qh[BATCH*SEQ*FD];
__device__ __nv_bfloat16 g_ql[BATCH*SEQ*FD];
__device__ __nv_bfloat16 g_kh[BATCH*SEQ*FD];
__device__ __nv_bfloat16 g_kl[BATCH*SEQ*FD];
__device__ __nv_bfloat16 g_vh[BATCH*SEQ*FD];
__device__ __nv_bfloat16 g_vl[BATCH*SEQ*FD];
__device__ __nv_bfloat16 g_ch[BATCH*SEQ*FD];
__device__ __nv_bfloat16 g_cl[BATCH*SEQ*FD];
__device__ __nv_bfloat16 g_wqh[FD*FD], g_wql[FD*FD];
__device__ __nv_bfloat16 g_wkh[FD*FD], g_wkl[FD*FD];
__device__ __nv_bfloat16 g_wvh[FD*FD], g_wvl[FD*FD];
__device__ __nv_bfloat16 g_woh[FD*FD], g_wol[FD*FD];
__device__ float g_o[BATCH*SEQ*FD];
__device__ unsigned g_adjb[SEQ * (SEQ/32)];

// ---------------- helpers ----------------
__device__ __forceinline__ u32 smem_u32(const void* p) {
  u32 a; asm("{ .reg .u64 t; cvta.to.shared.u64 t, %1; cvt.u32.u64 %0, t; }"
             : "=r"(a) : "l"(p)); return a;
}
__device__ __forceinline__ float ex2f(float x) {
  float r; asm("ex2.approx.f32 %0, %1;" : "=f"(r) : "f"(x)); return r;
}
__device__ __forceinline__ float rcpf(float x) {
  float r; asm("rcp.approx.f32 %0, %1;" : "=f"(r) : "f"(x)); return r;
}
__device__ __forceinline__ void split1(float x, __nv_bfloat16& h, __nv_bfloat16& l) {
  h = __float2bfloat16_rn(x);
  l = __float2bfloat16_rn(x - __bfloat162float(h));
}
__device__ __forceinline__ u32 packbf(__nv_bfloat16 e0, __nv_bfloat16 e1) {
  return ((u32)__bfloat16_as_ushort(e1) << 16) | (u32)__bfloat16_as_ushort(e0);
}
__device__ __forceinline__ void ldsm4(u32* r, u32 addr) {
  asm volatile("ldmatrix.sync.aligned.m8n8.x4.shared.b16 {%0,%1,%2,%3}, [%4];"
    : "=r"(r[0]), "=r"(r[1]), "=r"(r[2]), "=r"(r[3]) : "r"(addr));
}
__device__ __forceinline__ void ldsm4t(u32* r, u32 addr) {
  asm volatile("ldmatrix.sync.aligned.m8n8.x4.trans.shared.b16 {%0,%1,%2,%3}, [%4];"
    : "=r"(r[0]), "=r"(r[1]), "=r"(r[2]), "=r"(r[3]) : "r"(addr));
}
__device__ __forceinline__ void mma16816(float* d, const u32* a, u32 b0, u32 b1) {
  asm volatile("mma.sync.aligned.m16n8k16.row.col.f32.bf16.bf16.f32 "
    "{%0,%1,%2,%3}, {%4,%5,%6,%7}, {%8,%9}, {%0,%1,%2,%3};"
    : "+f"(d[0]), "+f"(d[1]), "+f"(d[2]), "+f"(d[3])
    : "r"(a[0]), "r"(a[1]), "r"(a[2]), "r"(a[3]), "r"(b0), "r"(b1));
}

// ---------------- prep: adjacency bit-pack ----------------
__global__ void pack_adj_kernel(const int* __restrict__ adj,
                                unsigned* __restrict__ adjb) {
  const int idx = blockIdx.x * 256 + threadIdx.x;
  const int4* p = (const int4*)(adj + (size_t)idx * 32);
  unsigned b = 0;
  #pragma unroll
  for (int u = 0; u < 8; u++) {
    int4 v = p[u];
    b |= (v.x != 0 ? 1u : 0u) << (u*4 + 0);
    b |= (v.y != 0 ? 1u : 0u) << (u*4 + 1);
    b |= (v.z != 0 ? 1u : 0u) << (u*4 + 2);
    b |= (v.w != 0 ? 1u : 0u) << (u*4 + 3);
  }
  adjb[idx] = b;
}

// ---------------- prep: split x into bf16 hi/lo planes ----------------
__global__ void split_x_kernel(const float* __restrict__ x,
                               __nv_bfloat16* __restrict__ xh,
                               __nv_bfloat16* __restrict__ xl) {
  const int i = (blockIdx.x * 256 + threadIdx.x) * 4;
  float4 v = *(const float4*)&x[i];
  __nv_bfloat16 h0,l0,h1,l1,h2,l2,h3,l3;
  split1(v.x,h0,l0); split1(v.y,h1,l1); split1(v.z,h2,l2); split1(v.w,h3,l3);
  *(u32*)&xh[i]   = packbf(h0,h1);
  *(u32*)&xh[i+2] = packbf(h2,h3);
  *(u32*)&xl[i]   = packbf(l0,l1);
  *(u32*)&xl[i+2] = packbf(l2,l3);
}

// ---------------- prep: split weights (Wq pre-scaled) ----------------
__global__ void split_w_kernel(
    const float* __restrict__ Wq, const float* __restrict__ Wk,
    const float* __restrict__ Wv, const float* __restrict__ Wo,
    __nv_bfloat16* __restrict__ wqh, __nv_bfloat16* __restrict__ wql,
    __nv_bfloat16* __restrict__ wkh, __nv_bfloat16* __restrict__ wkl,
    __nv_bfloat16* __restrict__ wvh, __nv_bfloat16* __restrict__ wvl,
    __nv_bfloat16* __restrict__ woh, __nv_bfloat16* __restrict__ wol,
    float qs) {
  const int m = blockIdx.y;
  const int i = blockIdx.x * 256 + threadIdx.x;
  const float* src = (m == 0) ? Wq : (m == 1) ? Wk : (m == 2) ? Wv : Wo;
  __nv_bfloat16* dh = (m == 0) ? wqh : (m == 1) ? wkh : (m == 2) ? wvh : woh;
  __nv_bfloat16* dl = (m == 0) ? wql : (m == 1) ? wkl : (m == 2) ? wvl : wol;
  float v = src[i] * ((m == 0) ? qs : 1.f);
  __nv_bfloat16 h, l; split1(v, h, l);
  dh[i] = h; dl[i] = l;
}

// ---------------- HMMA GEMM core: 128x128 tile, 256 threads ----------------
// C[m][n] = sum_k A[m][k]*W[n][k] (+bias, +resid) via 3-split bf16 mma
#define GPITCH 272
#define GOF_AH 0
#define GOF_AL (128*GPITCH)
#define GOF_WH (2*128*GPITCH)
#define GOF_WL (3*128*GPITCH)
#define GEMM_SMEM (4*128*GPITCH)   // 139264

template<int MODE>   // 0: split bf16 output; 1: fp32 + resid
__device__ __forceinline__ void hmma_gemm_core(
    const __nv_bfloat16* __restrict__ Ah, const __nv_bfloat16* __restrict__ Al,
    const __nv_bfloat16* __restrict__ Wh, const __nv_bfloat16* __restrict__ Wl,
    const float* __restrict__ bias, float sb,
    const float* __restrict__ resid, float* __restrict__ Cf,
    __nv_bfloat16* __restrict__ Ch, __nv_bfloat16* __restrict__ Cl,
    int m0, int n0, char* smem) {
  const u32 smb = smem_u32(smem);
  const int t = threadIdx.x;
  const int w = t >> 5, l = t & 31;
  const int wm = w & 3, wn = w >> 2;
  const int gr = l >> 2, tg = l & 3;

  float acc[2][8][4];
  #pragma unroll
  for (int i = 0; i < 2; i++)
    #pragma unroll
    for (int nt = 0; nt < 8; nt++)
      #pragma unroll
      for (int d = 0; d < 4; d++) acc[i][nt][d] = 0.f;

  for (int kc = 0; kc < 2; kc++) {
    __syncthreads();
    const int k0 = kc * 128;
    #pragma unroll
    for (int i = 0; i < 8; i++) {
      int idx = t + i * 256;              // 2048
      int r = idx >> 4, c = idx & 15;
      u32 so = r * GPITCH + c * 16;
      size_t ga = ((size_t)(m0 + r) * FD + k0) * 2 + c * 16;
      size_t gw = ((size_t)(n0 + r) * FD + k0) * 2 + c * 16;
      *(uint4*)(smem + GOF_AH + so) = *(const uint4*)((const char*)Ah + ga);
      *(uint4*)(smem + GOF_AL + so) = *(const uint4*)((const char*)Al + ga);
      *(uint4*)(smem + GOF_WH + so) = *(const uint4*)((const char*)Wh + gw);
      *(uint4*)(smem + GOF_WL + so) = *(const uint4*)((const char*)Wl + gw);
    }
    __syncthreads();

    const u32 lrow = (u32)(l & 15) * GPITCH;
    const u32 chi  = (u32)(l >> 4) * 16;
    #pragma unroll
    for (int ks = 0; ks < 8; ks++) {
      u32 bh[4][4], bl[4][4];
      #pragma unroll
      for (int g = 0; g < 4; g++) {
        u32 a = smb + GOF_WH + (u32)(wn * 64 + g * 16) * GPITCH + lrow + ks * 32 + chi;
        ldsm4(bh[g], a);
        ldsm4(bl[g], a + (GOF_WL - GOF_WH));
      }
      #pragma unroll
      for (int i = 0; i < 2; i++) {
        u32 a = smb + GOF_AH + (u32)(wm * 32 + i * 16) * GPITCH + lrow + ks * 32 + chi;
        u32 ah[4], al2[4];
        ldsm4(ah, a);
        ldsm4(al2, a + (GOF_AL - GOF_AH));
        #pragma unroll
        for (int g = 0; g < 4; g++) {
          mma16816(acc[i][2*g],   ah,  bh[g][0], bh[g][2]);
          mma16816(acc[i][2*g+1], ah,  bh[g][1], bh[g][3]);
          mma16816(acc[i][2*g],   ah,  bl[g][0], bl[g][2]);
          mma16816(acc[i][2*g+1], ah,  bl[g][1], bl[g][3]);
          mma16816(acc[i][2*g],   al2, bh[g][0], bh[g][2]);
          mma16816(acc[i][2*g+1], al2, bh[g][1], bh[g][3]);
        }
      }
    }
  }

  #pragma unroll
  for (int i = 0; i < 2; i++) {
    const int mrow = m0 + wm * 32 + i * 16 + gr;
    #pragma unroll
    for (int nt = 0; nt < 8; nt++) {
      const int n = n0 + wn * 64 + nt * 8 + 2 * tg;
      const float bx = bias[n] * sb, by = bias[n + 1] * sb;
      float c00 = acc[i][nt][0] + bx, c01 = acc[i][nt][1] + by;
      float c10 = acc[i][nt][2] + bx, c11 = acc[i][nt][3] + by;
      if (MODE == 0) {
        __nv_bfloat16 h0, l0, h1, l1;
        split1(c00, h0, l0); split1(c01, h1, l1);
        *(u32*)&Ch[(size_t)mrow * FD + n] = packbf(h0, h1);
        *(u32*)&Cl[(size_t)mrow * FD + n] = packbf(l0, l1);
        split1(c10, h0, l0); split1(c11, h1, l1);
        *(u32*)&Ch[(size_t)(mrow + 8) * FD + n] = packbf(h0, h1);
        *(u32*)&Cl[(size_t)(mrow + 8) * FD + n] = packbf(l0, l1);
      } else {
        float2 r0 = *(const float2*)&resid[(size_t)mrow * FD + n];
        float2 r1 = *(const float2*)&resid[(size_t)(mrow + 8) * FD + n];
        float2 o0; o0.x = c00 + r0.x; o0.y = c01 + r0.y;
        float2 o1; o1.x = c10 + r1.x; o1.y = c11 + r1.y;
        *(float2*)&Cf[(size_t)mrow * FD + n] = o0;
        *(float2*)&Cf[(size_t)(mrow + 8) * FD + n] = o1;
      }
    }
  }
}

__global__ void __launch_bounds__(256, 1) qkv_hmma_kernel(
    const __nv_bfloat16* __restrict__ xh, const __nv_bfloat16* __restrict__ xl,
    const __nv_bfloat16* __restrict__ wqh, const __nv_bfloat16* __restrict__ wql,
    const __nv_bfloat16* __restrict__ wkh, const __nv_bfloat16* __restrict__ wkl,
    const __nv_bfloat16* __restrict__ wvh, const __nv_bfloat16* __restrict__ wvl,
    const float* __restrict__ bq, const float* __restrict__ bk,
    const float* __restrict__ bv,
    __nv_bfloat16* __restrict__ qh, __nv_bfloat16* __restrict__ ql,
    __nv_bfloat16* __restrict__ kh, __nv_bfloat16* __restrict__ kl,
    __nv_bfloat16* __restrict__ vh, __nv_bfloat16* __restrict__ vl,
    float qs) {
  extern __shared__ __align__(16) char smem[];
  const int p = blockIdx.y >> 1, half = blockIdx.y & 1;
  const __nv_bfloat16* Wh = (p == 0) ? wqh : (p == 1) ? wkh : wvh;
  const __nv_bfloat16* Wl = (p == 0) ? wql : (p == 1) ? wkl : wvl;
  const float* bias = (p == 0) ? bq : (p == 1) ? bk : bv;
  __nv_bfloat16* Ch = (p == 0) ? qh : (p == 1) ? kh : vh;
  __nv_bfloat16* Cl = (p == 0) ? ql : (p == 1) ? kl : vl;
  const float sb = (p == 0) ? qs : 1.f;
  hmma_gemm_core<0>(xh, xl, Wh, Wl, bias, sb, nullptr, nullptr, Ch, Cl,
                    blockIdx.x * 128, half * 128, smem);
}

__global__ void __launch_bounds__(256, 1) o_hmma_kernel(
    const __nv_bfloat16* __restrict__ ch, const __nv_bfloat16* __restrict__ cl,
    const __nv_bfloat16* __restrict__ woh, const __nv_bfloat16* __restrict__ wol,
    const float* __restrict__ bo, const float* __restrict__ x,
    float* __restrict__ o) {
  extern __shared__ __align__(16) char smem[];
  hmma_gemm_core<1>(ch, cl, woh, wol, bo, 1.f, x, o, nullptr, nullptr,
                    blockIdx.x * 128, blockIdx.y * 128, smem);
}

// ---------------- HMMA attention ----------------
#define PITCH 144
#define OFF_QH 0
#define OFF_QL (OFF_QH + 128*PITCH)
#define OFF_KH (OFF_QL + 128*PITCH)
#define OFF_KL (OFF_KH + 256*PITCH)
#define OFF_VH (OFF_KL + 256*PITCH)
#define OFF_VL (OFF_VH + 256*PITCH)
#define OFF_ADJ (OFF_VL + 256*PITCH)
#define SM_ATTN (OFF_ADJ + 128*8*4)

__global__ void __launch_bounds__(256, 1) attn_hmma_kernel(
    const __nv_bfloat16* __restrict__ qh, const __nv_bfloat16* __restrict__ ql,
    const __nv_bfloat16* __restrict__ kh, const __nv_bfloat16* __restrict__ kl,
    const __nv_bfloat16* __restrict__ vh, const __nv_bfloat16* __restrict__ vl,
    const unsigned* __restrict__ adjb,
    __nv_bfloat16* __restrict__ ctxh, __nv_bfloat16* __restrict__ ctxl) {
  extern __shared__ __align__(16) char smem[];
  const u32 smb = smem_u32(smem);
  unsigned* adj_s = (unsigned*)(smem + OFF_ADJ);

  const int b  = blockIdx.z;
  const int h  = blockIdx.y;
  const int n0 = blockIdx.x * 128;
  const int t  = threadIdx.x;
  const int w  = t >> 5;
  const int l  = t & 31;
  const int gr = l >> 2, tg = l & 3;

  const float CLIP = 14.426950408889634f;
  const float ENEG = 4.5399929762484854e-05f;

  {
    const char* gqh = (const char*)(qh + ((size_t)b*SEQ + n0)*FD + h*DH);
    const char* gql = (const char*)(ql + ((size_t)b*SEQ + n0)*FD + h*DH);
    #pragma unroll
    for (int i = 0; i < 4; i++) {
      int idx = t + i * 256;
      int r = idx >> 3, c = idx & 7;
      *(uint4*)(smem + OFF_QH + r*PITCH + c*16) = *(const uint4*)(gqh + (size_t)r*512 + c*16);
      *(uint4*)(smem + OFF_QL + r*PITCH + c*16) = *(const uint4*)(gql + (size_t)r*512 + c*16);
    }
  }
  __syncthreads();

  u32 qfh[4][4], qfl[4][4];
  {
    const u32 rowoff = (u32)(w*16 + (l & 15)) * PITCH;
    const u32 coloff = (u32)((l >> 4) * 8) * 2;
    #pragma unroll
    for (int ks = 0; ks < 4; ks++) {
      u32 a = smb + OFF_QH + rowoff + ks*32 + coloff;
      ldsm4(qfh[ks], a);
      ldsm4(qfl[ks], a + (OFF_QL - OFF_QH));
    }
  }

  float ctxa[8][4];
  #pragma unroll
  for (int i = 0; i < 8; i++)
    #pragma unroll
    for (int d = 0; d < 4; d++) ctxa[i][d] = 0.f;

  const char* gkh = (const char*)(kh + ((size_t)b*SEQ)*FD + h*DH);
  const char* gkl = (const char*)(kl + ((size_t)b*SEQ)*FD + h*DH);
  const char* gvh = (const char*)(vh + ((size_t)b*SEQ)*FD + h*DH);
  const char* gvl = (const char*)(vl + ((size_t)b*SEQ)*FD + h*DH);

  for (int j = 0; j < NCHUNK; ++j) {
    __syncthreads();
    {
      const size_t gbase = (size_t)(j * CHK) * 512;
      #pragma unroll
      for (int i = 0; i < 8; i++) {
        int idx = t + i * 256;
        int r = idx >> 3, c = idx & 7;
        size_t go = gbase + (size_t)r*512 + c*16;
        u32 so = r*PITCH + c*16;
        *(uint4*)(smem + OFF_KH + so) = *(const uint4*)(gkh + go);
        *(uint4*)(smem + OFF_KL + so) = *(const uint4*)(gkl + go);
        *(uint4*)(smem + OFF_VH + so) = *(const uint4*)(gvh + go);
        *(uint4*)(smem + OFF_VL + so) = *(const uint4*)(gvl + go);
      }
      #pragma unroll
      for (int i = 0; i < 4; i++) {
        int idx = t + i * 256;
        int row = idx >> 3, wi = idx & 7;
        adj_s[idx] = adjb[(size_t)(n0 + row) * (SEQ/32) + j * 8 + wi];
      }
    }
    __syncthreads();

    float rs0 = 0.f, rs1 = 0.f;
    float cU[8][4];
    #pragma unroll
    for (int i = 0; i < 8; i++)
      #pragma unroll
      for (int d = 0; d < 4; d++) cU[i][d] = 0.f;

    #pragma unroll
    for (int kb = 0; kb < 4; kb++) {
      const int key0 = kb * 64;
      float S[8][4];
      #pragma unroll
      for (int i = 0; i < 8; i++)
        #pragma unroll
        for (int d = 0; d < 4; d++) S[i][d] = 0.f;

      const u32 lrow16 = (u32)(l & 15) * PITCH;
      const u32 chi = (u32)((l >> 4) * 8) * 2;
      #pragma unroll
      for (int ks = 0; ks < 4; ks++) {
        #pragma unroll
        for (int g = 0; g < 4; g++) {
          u32 a = smb + OFF_KH + (u32)(key0 + g*16)*PITCH + lrow16 + ks*32 + chi;
          u32 kf[4], kf2[4];
          ldsm4(kf,  a);
          ldsm4(kf2, a + (OFF_KL - OFF_KH));
          mma16816(S[2*g],   qfh[ks], kf[0],  kf[2]);
          mma16816(S[2*g+1], qfh[ks], kf[1],  kf[3]);
          mma16816(S[2*g],   qfh[ks], kf2[0], kf2[2]);
          mma16816(S[2*g+1], qfh[ks], kf2[1], kf2[3]);
          mma16816(S[2*g],   qfl[ks], kf[0],  kf[2]);
          mma16816(S[2*g+1], qfl[ks], kf[1],  kf[3]);
        }
      }

      const int lr0 = w*16 + gr;
      const u32 w00 = adj_s[lr0*8 + kb*2 + 0];
      const u32 w01 = adj_s[lr0*8 + kb*2 + 1];
      const u32 w10 = adj_s[(lr0+8)*8 + kb*2 + 0];
      const u32 w11 = adj_s[(lr0+8)*8 + kb*2 + 1];
      u32 Ph0[8], Ph1[8], Pl0[8], Pl1[8];
      #pragma unroll
      for (int nt = 0; nt < 8; nt++) {
        const u32 a0w = (nt < 4) ? w00 : w01;
        const u32 a1w = (nt < 4) ? w10 : w11;
        const int bit = (nt & 3) * 8 + 2 * tg;
        float x;
        x = fminf(fmaxf(S[nt][0], -CLIP), CLIP);
        float e00 = ((a0w >> bit) & 1u)     ? ex2f(x) : ENEG;
        x = fminf(fmaxf(S[nt][1], -CLIP), CLIP);
        float e01 = ((a0w >> (bit+1)) & 1u) ? ex2f(x) : ENEG;
        x = fminf(fmaxf(S[nt][2], -CLIP), CLIP);
        float e10 = ((a1w >> bit) & 1u)     ? ex2f(x) : ENEG;
        x = fminf(fmaxf(S[nt][3], -CLIP), CLIP);
        float e11 = ((a1w >> (bit+1)) & 1u) ? ex2f(x) : ENEG;
        rs0 += e00 + e01;
        rs1 += e10 + e11;
        __nv_bfloat16 h0,l0,h1,l1,h2,l2,h3,l3;
        split1(e00,h0,l0); split1(e01,h1,l1);
        split1(e10,h2,l2); split1(e11,h3,l3);
        Ph0[nt] = packbf(h0,h1); Pl0[nt] = packbf(l0,l1);
        Ph1[nt] = packbf(h2,h3); Pl1[nt] = packbf(l2,l3);
      }

      #pragma unroll
      for (int kt = 0; kt < 4; kt++) {
        u32 Ah[4] = { Ph0[2*kt], Ph1[2*kt], Ph0[2*kt+1], Ph1[2*kt+1] };
        u32 Al[4] = { Pl0[2*kt], Pl1[2*kt], Pl0[2*kt+1], Pl1[2*kt+1] };
        const u32 vrow = (u32)(key0 + kt*16) * PITCH + lrow16;
        #pragma unroll
        for (int dg = 0; dg < 4; dg++) {
          u32 a = smb + OFF_VH + vrow + dg*32 + chi;
          u32 vf[4], vf2[4];
          ldsm4t(vf,  a);
          ldsm4t(vf2, a + (OFF_VL - OFF_VH));
          mma16816(cU[2*dg],   Ah, vf[0],  vf[1]);
          mma16816(cU[2*dg+1], Ah, vf[2],  vf[3]);
          mma16816(cU[2*dg],   Ah, vf2[0], vf2[1]);
          mma16816(cU[2*dg+1], Ah, vf2[2], vf2[3]);
          mma16816(cU[2*dg],   Al, vf[0],  vf[1]);
          mma16816(cU[2*dg+1], Al, vf[2],  vf[3]);
        }
      }
    }

    float t0 = rs0;
    t0 += __shfl_xor_sync(0xFFFFFFFFu, t0, 1);
    t0 += __shfl_xor_sync(0xFFFFFFFFu, t0, 2);
    float t1 = rs1;
    t1 += __shfl_xor_sync(0xFFFFFFFFu, t1, 1);
    t1 += __shfl_xor_sync(0xFFFFFFFFu, t1, 2);
    const float r0 = rcpf(t0), r1 = rcpf(t1);
    #pragma unroll
    for (int i = 0; i < 8; i++) {
      ctxa[i][0] += cU[i][0] * r0;
      ctxa[i][1] += cU[i][1] * r0;
      ctxa[i][2] += cU[i][2] * r1;
      ctxa[i][3] += cU[i][3] * r1;
    }
  }

  // ---- store ctx as split bf16 planes ----
  {
    const int row0 = n0 + w*16 + gr;
    const size_t base0 = ((size_t)b*SEQ + row0) * FD + h*DH;
    const size_t base1 = base0 + (size_t)8 * FD;
    #pragma unroll
    for (int nt = 0; nt < 8; nt++) {
      const int cc = nt*8 + 2*tg;
      __nv_bfloat16 h0,l0,h1,l1;
      split1(ctxa[nt][0], h0, l0); split1(ctxa[nt][1], h1, l1);
      *(u32*)&ctxh[base0 + cc] = packbf(h0, h1);
      *(u32*)&ctxl[base0 + cc] = packbf(l0, l1);
      split1(ctxa[nt][2], h0, l0); split1(ctxa[nt][3], h1, l1);
      *(u32*)&ctxh[base1 + cc] = packbf(h0, h1);
      *(u32*)&ctxl[base1 + cc] = packbf(l0, l1);
    }
  }
}

// ---------------- LayerNorm ----------------
__global__ void ln_kernel(const float* __restrict__ o,
                          const float* __restrict__ gamma,
                          const float* __restrict__ beta,
                          float* __restrict__ out) {
  const int row = blockIdx.x;
  const int t = threadIdx.x;
  const int w = t >> 5, l = t & 31;
  const float val = o[(size_t)row * FD + t];

  float s1 = val, s2 = val * val;
  #pragma unroll
  for (int off = 16; off > 0; off >>= 1) {
    s1 += __shfl_xor_sync(0xFFFFFFFFu, s1, off);
    s2 += __shfl_xor_sync(0xFFFFFFFFu, s2, off);
  }
  __shared__ float rs1[8], rs2[8];
  __shared__ float mu_s, rstd_s;
  if (l == 0) { rs1[w] = s1; rs2[w] = s2; }
  __syncthreads();
  if (t == 0) {
    float S1 = 0.f, S2 = 0.f;
    #pragma unroll
    for (int i = 0; i < 8; i++) { S1 += rs1[i]; S2 += rs2[i]; }
    const float mu = S1 * (1.f / FD);
    const float var = S2 * (1.f / FD) - mu * mu;
    mu_s = mu;
    rstd_s = rsqrtf(var + 1e-5f);
  }
  __syncthreads();
  out[(size_t)row * FD + t] = (val - mu_s) * rstd_s * gamma[t] + beta[t];
}

// ---------------- launch ----------------
extern "C" void kernel_launch(void* const* d_in, const int* in_sizes, int n_in,
                              void* d_out, int out_size) {
  (void)in_sizes; (void)n_in; (void)out_size;
  const float* x     = (const float*)d_in[0];
  const int*   adj   = (const int*)  d_in[1];
  const float* Wq    = (const float*)d_in[2];
  const float* bq    = (const float*)d_in[3];
  const float* Wk    = (const float*)d_in[4];
  const float* bk    = (const float*)d_in[5];
  const float* Wv    = (const float*)d_in[6];
  const float* bv    = (const float*)d_in[7];
  const float* Wo    = (const float*)d_in[8];
  const float* bo    = (const float*)d_in[9];
  const float* gamma = (const float*)d_in[10];
  const float* beta  = (const float*)d_in[11];
  float* out = (float*)d_out;

  __nv_bfloat16 *pxh, *pxl, *pqh, *pql, *pkh, *pkl, *pvh, *pvl, *pch, *pcl;
  __nv_bfloat16 *pwqh, *pwql, *pwkh, *pwkl, *pwvh, *pwvl, *pwoh, *pwol;
  float *po;
  unsigned* padjb;
  cudaGetSymbolAddress((void**)&pxh, g_xh);
  cudaGetSymbolAddress((void**)&pxl, g_xl);
  cudaGetSymbolAddress((void**)&pqh, g_qh);
  cudaGetSymbolAddress((void**)&pql, g_ql);
  cudaGetSymbolAddress((void**)&pkh, g_kh);
  cudaGetSymbolAddress((void**)&pkl, g_kl);
  cudaGetSymbolAddress((void**)&pvh, g_vh);
  cudaGetSymbolAddress((void**)&pvl, g_vl);
  cudaGetSymbolAddress((void**)&pch, g_ch);
  cudaGetSymbolAddress((void**)&pcl, g_cl);
  cudaGetSymbolAddress((void**)&pwqh, g_wqh);
  cudaGetSymbolAddress((void**)&pwql, g_wql);
  cudaGetSymbolAddress((void**)&pwkh, g_wkh);
  cudaGetSymbolAddress((void**)&pwkl, g_wkl);
  cudaGetSymbolAddress((void**)&pwvh, g_wvh);
  cudaGetSymbolAddress((void**)&pwvl, g_wvl);
  cudaGetSymbolAddress((void**)&pwoh, g_woh);
  cudaGetSymbolAddress((void**)&pwol, g_wol);
  cudaGetSymbolAddress((void**)&po,   g_o);
  cudaGetSymbolAddress((void**)&padjb, g_adjb);

  const float QS = 0.18033688011112042f;   // 0.125 * log2(e)

  pack_adj_kernel<<<SEQ*(SEQ/32)/256, 256>>>(adj, padjb);
  split_x_kernel<<<(BATCH*SEQ*FD)/1024, 256>>>(x, pxh, pxl);
  split_w_kernel<<<dim3(FD*FD/256, 4), 256>>>(Wq, Wk, Wv, Wo,
      pwqh, pwql, pwkh, pwkl, pwvh, pwvl, pwoh, pwol, QS);

  cudaFuncSetAttribute(qkv_hmma_kernel, cudaFuncAttributeMaxDynamicSharedMemorySize,
                       GEMM_SMEM);
  qkv_hmma_kernel<<<dim3((BATCH*SEQ)/128, 6), 256, GEMM_SMEM>>>(
      pxh, pxl, pwqh, pwql, pwkh, pwkl, pwvh, pwvl, bq, bk, bv,
      pqh, pql, pkh, pkl, pvh, pvl, QS);

  cudaFuncSetAttribute(attn_hmma_kernel, cudaFuncAttributeMaxDynamicSharedMemorySize,
                       SM_ATTN);
  const dim3 ga(SEQ / 128, NH, BATCH);
  attn_hmma_kernel<<<ga, 256, SM_ATTN>>>(pqh, pql, pkh, pkl, pvh, pvl, padjb,
                                         pch, pcl);

  cudaFuncSetAttribute(o_hmma_kernel, cudaFuncAttributeMaxDynamicSharedMemorySize,
                       GEMM_SMEM);
  o_hmma_kernel<<<dim3((BATCH*SEQ)/128, 2), 256, GEMM_SMEM>>>(
      pch, pcl, pwoh, pwol, bo, x, po);

  ln_kernel<<<BATCH * SEQ, 256>>>(po, gamma, beta, out);
}

// round 7
// speedup vs baseline: 3.6673x; 1.2107x over previous
#include <cuda_runtime.h>
#include <cuda_bf16.h>
#include <cstdint>

#define BATCH 4
#define SEQ   2048
#define FD    256
#define NH    4
#define DH    64
#define CHK   256
#define NCHUNK 8

typedef unsigned long long ull;
typedef uint32_t u32;

// ---------------- device scratch ----------------
__device__ __nv_bfloat16 g_xh[BATCH*SEQ*FD];
__device__ __nv_bfloat16 g_xl[BATCH*SEQ*FD];
__device__ __nv_bfloat16 g_qh[BATCH*SEQ*FD];
__device__ __nv_bfloat16 g_ql[BATCH*SEQ*FD];
__device__ __nv_bfloat16 g_kh[BATCH*SEQ*FD];
__device__ __nv_bfloat16 g_kl[BATCH*SEQ*FD];
__device__ __nv_bfloat16 g_vh[BATCH*SEQ*FD];
__device__ __nv_bfloat16 g_vl[BATCH*SEQ*FD];
__device__ __nv_bfloat16 g_ch[BATCH*SEQ*FD];
__device__ __nv_bfloat16 g_cl[BATCH*SEQ*FD];
__device__ __nv_bfloat16 g_wqh[FD*FD], g_wql[FD*FD];
__device__ __nv_bfloat16 g_wkh[FD*FD], g_wkl[FD*FD];
__device__ __nv_bfloat16 g_wvh[FD*FD], g_wvl[FD*FD];
__device__ __nv_bfloat16 g_woh[FD*FD], g_wol[FD*FD];
__device__ float g_o[BATCH*SEQ*FD];
__device__ unsigned g_adjb[SEQ * (SEQ/32)];

// ---------------- helpers ----------------
__device__ __forceinline__ u32 smem_u32(const void* p) {
  u32 a; asm("{ .reg .u64 t; cvta.to.shared.u64 t, %1; cvt.u32.u64 %0, t; }"
             : "=r"(a) : "l"(p)); return a;
}
__device__ __forceinline__ float ex2f(float x) {
  float r; asm("ex2.approx.f32 %0, %1;" : "=f"(r) : "f"(x)); return r;
}
__device__ __forceinline__ float rcpf(float x) {
  float r; asm("rcp.approx.f32 %0, %1;" : "=f"(r) : "f"(x)); return r;
}
__device__ __forceinline__ void split1(float x, __nv_bfloat16& h, __nv_bfloat16& l) {
  h = __float2bfloat16_rn(x);
  l = __float2bfloat16_rn(x - __bfloat162float(h));
}
__device__ __forceinline__ u32 packbf(__nv_bfloat16 e0, __nv_bfloat16 e1) {
  return ((u32)__bfloat16_as_ushort(e1) << 16) | (u32)__bfloat16_as_ushort(e0);
}
// Dekker truncation split of a pair: hw = packed bf16 hi (truncate),
// lw = packed bf16 lo (round-nearest). x = hi + lo exact to ~2^-17.
__device__ __forceinline__ void tsplit2(float x0, float x1, u32& hw, u32& lw) {
  u32 b0 = __float_as_uint(x0), b1 = __float_as_uint(x1);
  u32 h0 = b0 & 0xFFFF0000u, h1 = b1 & 0xFFFF0000u;
  hw = (b0 >> 16) | h1;
  float l0 = x0 - __uint_as_float(h0);
  float l1 = x1 - __uint_as_float(h1);
  asm("cvt.rn.bf16x2.f32 %0, %1, %2;" : "=r"(lw) : "f"(l1), "f"(l0));
}
__device__ __forceinline__ void ldsm4(u32* r, u32 addr) {
  asm volatile("ldmatrix.sync.aligned.m8n8.x4.shared.b16 {%0,%1,%2,%3}, [%4];"
    : "=r"(r[0]), "=r"(r[1]), "=r"(r[2]), "=r"(r[3]) : "r"(addr));
}
__device__ __forceinline__ void ldsm4t(u32* r, u32 addr) {
  asm volatile("ldmatrix.sync.aligned.m8n8.x4.trans.shared.b16 {%0,%1,%2,%3}, [%4];"
    : "=r"(r[0]), "=r"(r[1]), "=r"(r[2]), "=r"(r[3]) : "r"(addr));
}
__device__ __forceinline__ void mma16816(float* d, const u32* a, u32 b0, u32 b1) {
  asm volatile("mma.sync.aligned.m16n8k16.row.col.f32.bf16.bf16.f32 "
    "{%0,%1,%2,%3}, {%4,%5,%6,%7}, {%8,%9}, {%0,%1,%2,%3};"
    : "+f"(d[0]), "+f"(d[1]), "+f"(d[2]), "+f"(d[3])
    : "r"(a[0]), "r"(a[1]), "r"(a[2]), "r"(a[3]), "r"(b0), "r"(b1));
}
#define CPA16(dst, src) \
  asm volatile("cp.async.cg.shared.global [%0], [%1], 16;" \
               :: "r"(dst), "l"(src) : "memory")
#define CPA_FENCE() do { \
  asm volatile("cp.async.commit_group;" ::: "memory"); \
  asm volatile("cp.async.wait_group 0;" ::: "memory"); \
} while (0)

// ---------------- prep kernels ----------------
__global__ void pack_adj_kernel(const int* __restrict__ adj,
                                unsigned* __restrict__ adjb) {
  const int idx = blockIdx.x * 256 + threadIdx.x;
  const int4* p = (const int4*)(adj + (size_t)idx * 32);
  unsigned b = 0;
  #pragma unroll
  for (int u = 0; u < 8; u++) {
    int4 v = p[u];
    b |= (v.x != 0 ? 1u : 0u) << (u*4 + 0);
    b |= (v.y != 0 ? 1u : 0u) << (u*4 + 1);
    b |= (v.z != 0 ? 1u : 0u) << (u*4 + 2);
    b |= (v.w != 0 ? 1u : 0u) << (u*4 + 3);
  }
  adjb[idx] = b;
}

__global__ void split_x_kernel(const float* __restrict__ x,
                               __nv_bfloat16* __restrict__ xh,
                               __nv_bfloat16* __restrict__ xl) {
  const int i = (blockIdx.x * 256 + threadIdx.x) * 4;
  float4 v = *(const float4*)&x[i];
  u32 h0, l0, h1, l1;
  tsplit2(v.x, v.y, h0, l0);
  tsplit2(v.z, v.w, h1, l1);
  *(u32*)&xh[i]   = h0; *(u32*)&xh[i+2] = h1;
  *(u32*)&xl[i]   = l0; *(u32*)&xl[i+2] = l1;
}

__global__ void split_w_kernel(
    const float* __restrict__ Wq, const float* __restrict__ Wk,
    const float* __restrict__ Wv, const float* __restrict__ Wo,
    __nv_bfloat16* __restrict__ wqh, __nv_bfloat16* __restrict__ wql,
    __nv_bfloat16* __restrict__ wkh, __nv_bfloat16* __restrict__ wkl,
    __nv_bfloat16* __restrict__ wvh, __nv_bfloat16* __restrict__ wvl,
    __nv_bfloat16* __restrict__ woh, __nv_bfloat16* __restrict__ wol,
    float qs) {
  const int m = blockIdx.y;
  const int i = (blockIdx.x * 256 + threadIdx.x) * 2;
  const float* src = (m == 0) ? Wq : (m == 1) ? Wk : (m == 2) ? Wv : Wo;
  __nv_bfloat16* dh = (m == 0) ? wqh : (m == 1) ? wkh : (m == 2) ? wvh : woh;
  __nv_bfloat16* dl = (m == 0) ? wql : (m == 1) ? wkl : (m == 2) ? wvl : wol;
  const float s = (m == 0) ? qs : 1.f;
  float2 v = *(const float2*)&src[i];
  u32 hw, lw;
  tsplit2(v.x * s, v.y * s, hw, lw);
  *(u32*)&dh[i] = hw;
  *(u32*)&dl[i] = lw;
}

// ---------------- HMMA GEMM core: 64x128 tile, 128 threads, 2 CTAs/SM ------
#define GP 144
#define GOF_AH 0
#define GOF_AL 9216
#define GOF_WH 18432
#define GOF_WL 36864
#define GEMM_SMEM 55296

template<int MODE>   // 0: split bf16 output; 1: fp32 + resid
__device__ __forceinline__ void hmma_gemm_core(
    const __nv_bfloat16* __restrict__ Ah, const __nv_bfloat16* __restrict__ Al,
    const __nv_bfloat16* __restrict__ Wh, const __nv_bfloat16* __restrict__ Wl,
    const float* __restrict__ bias, float sb,
    const float* __restrict__ resid, float* __restrict__ Cf,
    __nv_bfloat16* __restrict__ Ch, __nv_bfloat16* __restrict__ Cl,
    int m0, int n0g, char* smem) {
  const u32 smb = smem_u32(smem);
  const int t = threadIdx.x;
  const int w = t >> 5, l = t & 31;
  const int gr = l >> 2, tg = l & 3;

  float acc[16][4];
  #pragma unroll
  for (int nt = 0; nt < 16; nt++)
    #pragma unroll
    for (int d = 0; d < 4; d++) acc[nt][d] = 0.f;

  for (int kc = 0; kc < 4; kc++) {
    const int k0 = kc * 64;
    __syncthreads();
    #pragma unroll
    for (int i = 0; i < 4; i++) {
      int idx = t + i * 128;
      int r = idx >> 3, c = idx & 7;
      u32 so = r * GP + c * 16;
      size_t ga = ((size_t)(m0 + r) * FD + k0) * 2 + c * 16;
      CPA16(smb + GOF_AH + so, (const char*)Ah + ga);
      CPA16(smb + GOF_AL + so, (const char*)Al + ga);
    }
    #pragma unroll
    for (int i = 0; i < 8; i++) {
      int idx = t + i * 128;
      int r = idx >> 3, c = idx & 7;
      u32 so = r * GP + c * 16;
      size_t gw = ((size_t)(n0g + r) * FD + k0) * 2 + c * 16;
      CPA16(smb + GOF_WH + so, (const char*)Wh + gw);
      CPA16(smb + GOF_WL + so, (const char*)Wl + gw);
    }
    CPA_FENCE();
    __syncthreads();

    const u32 lrow = (u32)(l & 15) * GP;
    const u32 chi  = (u32)(l >> 4) * 16;
    #pragma unroll
    for (int ks = 0; ks < 4; ks++) {
      u32 aa = smb + GOF_AH + (u32)(w * 16) * GP + lrow + ks * 32 + chi;
      u32 ah[4], al2[4];
      ldsm4(ah, aa);
      ldsm4(al2, aa + (GOF_AL - GOF_AH));
      #pragma unroll
      for (int g = 0; g < 8; g++) {
        u32 wa = smb + GOF_WH + (u32)(g * 16) * GP + lrow + ks * 32 + chi;
        u32 bh[4], bl[4];
        ldsm4(bh, wa);
        ldsm4(bl, wa + (GOF_WL - GOF_WH));
        mma16816(acc[2*g],   ah,  bh[0], bh[2]);
        mma16816(acc[2*g+1], ah,  bh[1], bh[3]);
        mma16816(acc[2*g],   ah,  bl[0], bl[2]);
        mma16816(acc[2*g+1], ah,  bl[1], bl[3]);
        mma16816(acc[2*g],   al2, bh[0], bh[2]);
        mma16816(acc[2*g+1], al2, bh[1], bh[3]);
      }
    }
  }

  const int mrow = m0 + w * 16 + gr;
  #pragma unroll
  for (int nt = 0; nt < 16; nt++) {
    const int n = n0g + nt * 8 + 2 * tg;
    const float bx = bias[n] * sb, by = bias[n + 1] * sb;
    float c00 = acc[nt][0] + bx, c01 = acc[nt][1] + by;
    float c10 = acc[nt][2] + bx, c11 = acc[nt][3] + by;
    if (MODE == 0) {
      u32 hw, lw;
      tsplit2(c00, c01, hw, lw);
      *(u32*)&Ch[(size_t)mrow * FD + n] = hw;
      *(u32*)&Cl[(size_t)mrow * FD + n] = lw;
      tsplit2(c10, c11, hw, lw);
      *(u32*)&Ch[(size_t)(mrow + 8) * FD + n] = hw;
      *(u32*)&Cl[(size_t)(mrow + 8) * FD + n] = lw;
    } else {
      float2 r0 = *(const float2*)&resid[(size_t)mrow * FD + n];
      float2 r1 = *(const float2*)&resid[(size_t)(mrow + 8) * FD + n];
      float2 o0; o0.x = c00 + r0.x; o0.y = c01 + r0.y;
      float2 o1; o1.x = c10 + r1.x; o1.y = c11 + r1.y;
      *(float2*)&Cf[(size_t)mrow * FD + n] = o0;
      *(float2*)&Cf[(size_t)(mrow + 8) * FD + n] = o1;
    }
  }
}

__global__ void __launch_bounds__(128, 2) qkv_hmma_kernel(
    const __nv_bfloat16* __restrict__ xh, const __nv_bfloat16* __restrict__ xl,
    const __nv_bfloat16* __restrict__ wqh, const __nv_bfloat16* __restrict__ wql,
    const __nv_bfloat16* __restrict__ wkh, const __nv_bfloat16* __restrict__ wkl,
    const __nv_bfloat16* __restrict__ wvh, const __nv_bfloat16* __restrict__ wvl,
    const float* __restrict__ bq, const float* __restrict__ bk,
    const float* __restrict__ bv,
    __nv_bfloat16* __restrict__ qh, __nv_bfloat16* __restrict__ ql,
    __nv_bfloat16* __restrict__ kh, __nv_bfloat16* __restrict__ kl,
    __nv_bfloat16* __restrict__ vh, __nv_bfloat16* __restrict__ vl,
    float qs) {
  extern __shared__ __align__(16) char smem[];
  const int p = blockIdx.y >> 1, half = blockIdx.y & 1;
  const __nv_bfloat16* Wh = (p == 0) ? wqh : (p == 1) ? wkh : wvh;
  const __nv_bfloat16* Wl = (p == 0) ? wql : (p == 1) ? wkl : wvl;
  const float* bias = (p == 0) ? bq : (p == 1) ? bk : bv;
  __nv_bfloat16* Ch = (p == 0) ? qh : (p == 1) ? kh : vh;
  __nv_bfloat16* Cl = (p == 0) ? ql : (p == 1) ? kl : vl;
  const float sb = (p == 0) ? qs : 1.f;
  hmma_gemm_core<0>(xh, xl, Wh, Wl, bias, sb, nullptr, nullptr, Ch, Cl,
                    blockIdx.x * 64, half * 128, smem);
}

__global__ void __launch_bounds__(128, 2) o_hmma_kernel(
    const __nv_bfloat16* __restrict__ ch, const __nv_bfloat16* __restrict__ cl,
    const __nv_bfloat16* __restrict__ woh, const __nv_bfloat16* __restrict__ wol,
    const float* __restrict__ bo, const float* __restrict__ x,
    float* __restrict__ o) {
  extern __shared__ __align__(16) char smem[];
  hmma_gemm_core<1>(ch, cl, woh, wol, bo, 1.f, x, o, nullptr, nullptr,
                    blockIdx.x * 64, blockIdx.y * 128, smem);
}

// ---------------- HMMA attention: 128 threads, Q-tile 64, 2 CTAs/SM --------
#define AP 144
#define AOF_QH 0
#define AOF_QL 9216
#define AOF_KH 18432
#define AOF_KL (AOF_KH + 18432)
#define AOF_VH (AOF_KL + 18432)
#define AOF_VL (AOF_VH + 18432)
#define AOF_ADJ (AOF_VL + 18432)      // 92160
#define SM_ATTN (AOF_ADJ + 2048)      // 94208

__global__ void __launch_bounds__(128, 2) attn_hmma_kernel(
    const __nv_bfloat16* __restrict__ qh, const __nv_bfloat16* __restrict__ ql,
    const __nv_bfloat16* __restrict__ kh, const __nv_bfloat16* __restrict__ kl,
    const __nv_bfloat16* __restrict__ vh, const __nv_bfloat16* __restrict__ vl,
    const unsigned* __restrict__ adjb,
    __nv_bfloat16* __restrict__ ctxh, __nv_bfloat16* __restrict__ ctxl) {
  extern __shared__ __align__(16) char smem[];
  const u32 smb = smem_u32(smem);
  unsigned* adj_s = (unsigned*)(smem + AOF_ADJ);

  const int b  = blockIdx.z;
  const int h  = blockIdx.y;
  const int n0 = blockIdx.x * 64;
  const int t  = threadIdx.x;
  const int w  = t >> 5;
  const int l  = t & 31;
  const int gr = l >> 2, tg = l & 3;

  const float CLIP = 14.426950408889634f;
  const float ENEG = 4.5399929762484854e-05f;

  // ---- stage Q (hi/lo), 64 rows x 64 bf16 ----
  {
    const char* gqh = (const char*)(qh + ((size_t)b*SEQ + n0)*FD + h*DH);
    const char* gql = (const char*)(ql + ((size_t)b*SEQ + n0)*FD + h*DH);
    #pragma unroll
    for (int i = 0; i < 4; i++) {
      int idx = t + i * 128;
      int r = idx >> 3, c = idx & 7;
      u32 so = r * AP + c * 16;
      CPA16(smb + AOF_QH + so, gqh + (size_t)r*512 + c*16);
      CPA16(smb + AOF_QL + so, gql + (size_t)r*512 + c*16);
    }
    CPA_FENCE();
  }
  __syncthreads();

  u32 qfh[4][4], qfl[4][4];
  {
    const u32 rowoff = (u32)(w*16 + (l & 15)) * AP;
    const u32 coloff = (u32)((l >> 4) * 8) * 2;
    #pragma unroll
    for (int ks = 0; ks < 4; ks++) {
      u32 a = smb + AOF_QH + rowoff + ks*32 + coloff;
      ldsm4(qfh[ks], a);
      ldsm4(qfl[ks], a + (AOF_QL - AOF_QH));
    }
  }

  float ctxa[8][4];
  #pragma unroll
  for (int i = 0; i < 8; i++)
    #pragma unroll
    for (int d = 0; d < 4; d++) ctxa[i][d] = 0.f;

  const char* gkh = (const char*)(kh + ((size_t)b*SEQ)*FD + h*DH);
  const char* gkl = (const char*)(kl + ((size_t)b*SEQ)*FD + h*DH);
  const char* gvh = (const char*)(vh + ((size_t)b*SEQ)*FD + h*DH);
  const char* gvl = (const char*)(vl + ((size_t)b*SEQ)*FD + h*DH);

  const int lr0 = w*16 + gr;

  for (int j = 0; j < NCHUNK; ++j) {
    __syncthreads();   // all warps done with prev chunk (adj + K/V reads)

    // stage adjacency bits for this chunk: [64 rows][8 words]
    #pragma unroll
    for (int i = 0; i < 4; i++) {
      int idx = t + i * 128;
      int row = idx >> 3, wi = idx & 7;
      adj_s[idx] = adjb[(size_t)(n0 + row) * (SEQ/32) + j * 8 + wi];
    }

    float rs0 = 0.f, rs1 = 0.f;
    float cU[8][4];
    #pragma unroll
    for (int i = 0; i < 8; i++)
      #pragma unroll
      for (int d = 0; d < 4; d++) cU[i][d] = 0.f;

    for (int hf = 0; hf < 2; hf++) {
      if (hf) __syncthreads();   // protect K/V before restage
      // stage K/V half-chunk: 128 keys x 64 bf16, hi/lo
      {
        const size_t gb = (size_t)(j * CHK + hf * 128) * 512;
        #pragma unroll
        for (int i = 0; i < 8; i++) {
          int idx = t + i * 128;
          int r = idx >> 3, c = idx & 7;
          size_t go = gb + (size_t)r*512 + c*16;
          u32 so = r * AP + c * 16;
          CPA16(smb + AOF_KH + so, gkh + go);
          CPA16(smb + AOF_KL + so, gkl + go);
          CPA16(smb + AOF_VH + so, gvh + go);
          CPA16(smb + AOF_VL + so, gvl + go);
        }
        CPA_FENCE();
      }
      __syncthreads();

      #pragma unroll
      for (int kb = 0; kb < 2; kb++) {
        const int key0 = kb * 64;
        float S[8][4];
        #pragma unroll
        for (int i = 0; i < 8; i++)
          #pragma unroll
          for (int d = 0; d < 4; d++) S[i][d] = 0.f;

        const u32 lrow16 = (u32)(l & 15) * AP;
        const u32 chi = (u32)((l >> 4) * 8) * 2;
        #pragma unroll
        for (int ks = 0; ks < 4; ks++) {
          #pragma unroll
          for (int g = 0; g < 4; g++) {
            u32 a = smb + AOF_KH + (u32)(key0 + g*16)*AP + lrow16 + ks*32 + chi;
            u32 kf[4], kf2[4];
            ldsm4(kf,  a);
            ldsm4(kf2, a + (AOF_KL - AOF_KH));
            mma16816(S[2*g],   qfh[ks], kf[0],  kf[2]);
            mma16816(S[2*g+1], qfh[ks], kf[1],  kf[3]);
            mma16816(S[2*g],   qfh[ks], kf2[0], kf2[2]);
            mma16816(S[2*g+1], qfh[ks], kf2[1], kf2[3]);
            mma16816(S[2*g],   qfl[ks], kf[0],  kf[2]);
            mma16816(S[2*g+1], qfl[ks], kf[1],  kf[3]);
          }
        }

        const int wbase = lr0*8 + hf*4 + kb*2;
        const u32 w00 = adj_s[wbase + 0];
        const u32 w01 = adj_s[wbase + 1];
        const u32 w10 = adj_s[wbase + 64 + 0];
        const u32 w11 = adj_s[wbase + 64 + 1];
        u32 Ph0[8], Ph1[8], Pl0[8], Pl1[8];
        #pragma unroll
        for (int nt = 0; nt < 8; nt++) {
          const u32 a0w = (nt < 4) ? w00 : w01;
          const u32 a1w = (nt < 4) ? w10 : w11;
          const int bit = (nt & 3) * 8 + 2 * tg;
          float x;
          x = fminf(fmaxf(S[nt][0], -CLIP), CLIP);
          float e00 = ((a0w >> bit) & 1u)     ? ex2f(x) : ENEG;
          x = fminf(fmaxf(S[nt][1], -CLIP), CLIP);
          float e01 = ((a0w >> (bit+1)) & 1u) ? ex2f(x) : ENEG;
          x = fminf(fmaxf(S[nt][2], -CLIP), CLIP);
          float e10 = ((a1w >> bit) & 1u)     ? ex2f(x) : ENEG;
          x = fminf(fmaxf(S[nt][3], -CLIP), CLIP);
          float e11 = ((a1w >> (bit+1)) & 1u) ? ex2f(x) : ENEG;
          rs0 += e00 + e01;
          rs1 += e10 + e11;
          tsplit2(e00, e01, Ph0[nt], Pl0[nt]);
          tsplit2(e10, e11, Ph1[nt], Pl1[nt]);
        }

        #pragma unroll
        for (int kt = 0; kt < 4; kt++) {
          u32 Ah[4] = { Ph0[2*kt], Ph1[2*kt], Ph0[2*kt+1], Ph1[2*kt+1] };
          u32 Al[4] = { Pl0[2*kt], Pl1[2*kt], Pl0[2*kt+1], Pl1[2*kt+1] };
          const u32 vrow = (u32)(key0 + kt*16) * AP + lrow16;
          #pragma unroll
          for (int dg = 0; dg < 4; dg++) {
            u32 a = smb + AOF_VH + vrow + dg*32 + chi;
            u32 vf[4], vf2[4];
            ldsm4t(vf,  a);
            ldsm4t(vf2, a + (AOF_VL - AOF_VH));
            mma16816(cU[2*dg],   Ah, vf[0],  vf[1]);
            mma16816(cU[2*dg+1], Ah, vf[2],  vf[3]);
            mma16816(cU[2*dg],   Ah, vf2[0], vf2[1]);
            mma16816(cU[2*dg+1], Ah, vf2[2], vf2[3]);
            mma16816(cU[2*dg],   Al, vf[0],  vf[1]);
            mma16816(cU[2*dg+1], Al, vf[2],  vf[3]);
          }
        }
      }
    }

    // per-chunk softmax normalization
    float t0 = rs0;
    t0 += __shfl_xor_sync(0xFFFFFFFFu, t0, 1);
    t0 += __shfl_xor_sync(0xFFFFFFFFu, t0, 2);
    float t1 = rs1;
    t1 += __shfl_xor_sync(0xFFFFFFFFu, t1, 1);
    t1 += __shfl_xor_sync(0xFFFFFFFFu, t1, 2);
    const float r0 = rcpf(t0), r1 = rcpf(t1);
    #pragma unroll
    for (int i = 0; i < 8; i++) {
      ctxa[i][0] += cU[i][0] * r0;
      ctxa[i][1] += cU[i][1] * r0;
      ctxa[i][2] += cU[i][2] * r1;
      ctxa[i][3] += cU[i][3] * r1;
    }
  }

  // ---- store ctx as split bf16 planes ----
  {
    const int row0 = n0 + w*16 + gr;
    const size_t base0 = ((size_t)b*SEQ + row0) * FD + h*DH;
    const size_t base1 = base0 + (size_t)8 * FD;
    #pragma unroll
    for (int nt = 0; nt < 8; nt++) {
      const int cc = nt*8 + 2*tg;
      u32 hw, lw;
      tsplit2(ctxa[nt][0], ctxa[nt][1], hw, lw);
      *(u32*)&ctxh[base0 + cc] = hw;
      *(u32*)&ctxl[base0 + cc] = lw;
      tsplit2(ctxa[nt][2], ctxa[nt][3], hw, lw);
      *(u32*)&ctxh[base1 + cc] = hw;
      *(u32*)&ctxl[base1 + cc] = lw;
    }
  }
}

// ---------------- LayerNorm ----------------
__global__ void ln_kernel(const float* __restrict__ o,
                          const float* __restrict__ gamma,
                          const float* __restrict__ beta,
                          float* __restrict__ out) {
  const int row = blockIdx.x;
  const int t = threadIdx.x;
  const int w = t >> 5, l = t & 31;
  const float val = o[(size_t)row * FD + t];

  float s1 = val, s2 = val * val;
  #pragma unroll
  for (int off = 16; off > 0; off >>= 1) {
    s1 += __shfl_xor_sync(0xFFFFFFFFu, s1, off);
    s2 += __shfl_xor_sync(0xFFFFFFFFu, s2, off);
  }
  __shared__ float rs1[8], rs2[8];
  __shared__ float mu_s, rstd_s;
  if (l == 0) { rs1[w] = s1; rs2[w] = s2; }
  __syncthreads();
  if (t == 0) {
    float S1 = 0.f, S2 = 0.f;
    #pragma unroll
    for (int i = 0; i < 8; i++) { S1 += rs1[i]; S2 += rs2[i]; }
    const float mu = S1 * (1.f / FD);
    const float var = S2 * (1.f / FD) - mu * mu;
    mu_s = mu;
    rstd_s = rsqrtf(var + 1e-5f);
  }
  __syncthreads();
  out[(size_t)row * FD + t] = (val - mu_s) * rstd_s * gamma[t] + beta[t];
}

// ---------------- launch ----------------
extern "C" void kernel_launch(void* const* d_in, const int* in_sizes, int n_in,
                              void* d_out, int out_size) {
  (void)in_sizes; (void)n_in; (void)out_size;
  const float* x     = (const float*)d_in[0];
  const int*   adj   = (const int*)  d_in[1];
  const float* Wq    = (const float*)d_in[2];
  const float* bq    = (const float*)d_in[3];
  const float* Wk    = (const float*)d_in[4];
  const float* bk    = (const float*)d_in[5];
  const float* Wv    = (const float*)d_in[6];
  const float* bv    = (const float*)d_in[7];
  const float* Wo    = (const float*)d_in[8];
  const float* bo    = (const float*)d_in[9];
  const float* gamma = (const float*)d_in[10];
  const float* beta  = (const float*)d_in[11];
  float* out = (float*)d_out;

  __nv_bfloat16 *pxh, *pxl, *pqh, *pql, *pkh, *pkl, *pvh, *pvl, *pch, *pcl;
  __nv_bfloat16 *pwqh, *pwql, *pwkh, *pwkl, *pwvh, *pwvl, *pwoh, *pwol;
  float *po;
  unsigned* padjb;
  cudaGetSymbolAddress((void**)&pxh, g_xh);
  cudaGetSymbolAddress((void**)&pxl, g_xl);
  cudaGetSymbolAddress((void**)&pqh, g_qh);
  cudaGetSymbolAddress((void**)&pql, g_ql);
  cudaGetSymbolAddress((void**)&pkh, g_kh);
  cudaGetSymbolAddress((void**)&pkl, g_kl);
  cudaGetSymbolAddress((void**)&pvh, g_vh);
  cudaGetSymbolAddress((void**)&pvl, g_vl);
  cudaGetSymbolAddress((void**)&pch, g_ch);
  cudaGetSymbolAddress((void**)&pcl, g_cl);
  cudaGetSymbolAddress((void**)&pwqh, g_wqh);
  cudaGetSymbolAddress((void**)&pwql, g_wql);
  cudaGetSymbolAddress((void**)&pwkh, g_wkh);
  cudaGetSymbolAddress((void**)&pwkl, g_wkl);
  cudaGetSymbolAddress((void**)&pwvh, g_wvh);
  cudaGetSymbolAddress((void**)&pwvl, g_wvl);
  cudaGetSymbolAddress((void**)&pwoh, g_woh);
  cudaGetSymbolAddress((void**)&pwol, g_wol);
  cudaGetSymbolAddress((void**)&po,   g_o);
  cudaGetSymbolAddress((void**)&padjb, g_adjb);

  const float QS = 0.18033688011112042f;   // 0.125 * log2(e)

  pack_adj_kernel<<<SEQ*(SEQ/32)/256, 256>>>(adj, padjb);
  split_x_kernel<<<(BATCH*SEQ*FD)/1024, 256>>>(x, pxh, pxl);
  split_w_kernel<<<dim3(FD*FD/512, 4), 256>>>(Wq, Wk, Wv, Wo,
      pwqh, pwql, pwkh, pwkl, pwvh, pwvl, pwoh, pwol, QS);

  cudaFuncSetAttribute(qkv_hmma_kernel, cudaFuncAttributeMaxDynamicSharedMemorySize,
                       GEMM_SMEM);
  qkv_hmma_kernel<<<dim3((BATCH*SEQ)/64, 6), 128, GEMM_SMEM>>>(
      pxh, pxl, pwqh, pwql, pwkh, pwkl, pwvh, pwvl, bq, bk, bv,
      pqh, pql, pkh, pkl, pvh, pvl, QS);

  cudaFuncSetAttribute(attn_hmma_kernel, cudaFuncAttributeMaxDynamicSharedMemorySize,
                       SM_ATTN);
  const dim3 ga(SEQ / 64, NH, BATCH);
  attn_hmma_kernel<<<ga, 128, SM_ATTN>>>(pqh, pql, pkh, pkl, pvh, pvl, padjb,
                                         pch, pcl);

  cudaFuncSetAttribute(o_hmma_kernel, cudaFuncAttributeMaxDynamicSharedMemorySize,
                       GEMM_SMEM);
  o_hmma_kernel<<<dim3((BATCH*SEQ)/64, 2), 128, GEMM_SMEM>>>(
      pch, pcl, pwoh, pwol, bo, x, po);

  ln_kernel<<<BATCH * SEQ, 256>>>(po, gamma, beta, out);
}